// round 2
// baseline (speedup 1.0000x reference)
#include <cuda_runtime.h>
#include <cuda_bf16.h>
#include <cstddef>

// ---------------------------------------------------------------------------
// Problem constants (fixed shapes)
// ---------------------------------------------------------------------------
#define BATCH   4
#define EMB     256
#define S_TOT   120136
#define OUT_TOK 25672

// token offsets of depth segments 1..8 in the S axis
// OFF = {0, 8, 72, 328, 1352, 5448, 21832, 54600, 120136}
#define OFF3    328      // start of depth-4 segment == end of identity segs
#define OFF4    1352
#define OFF5    5448
#define OFF6    21832
#define OFF7    54600

#define EMB_TOK (S_TOT - OFF3)   // 119808 tokens stored in scratch

// per-segment token offsets inside g_emb (token units)
#define E4_OFF  0
#define E5_OFF  (OFF4 - OFF3)    // 1024
#define E6_OFF  (OFF5 - OFF3)    // 5120
#define E7_OFF  (OFF6 - OFF3)    // 21504
#define E8_OFF  (OFF7 - OFF3)    // 54272

// output region offsets (tokens)
#define O4 328
#define O5 584
#define O6 1096
#define O7 5192
#define O8 9288

// mixed counts (scatter list capacities)
#define MIX5 2048
#define MIX6 4096
#define MIX7 8192

// ---------------------------------------------------------------------------
// Scratch (static __device__ memory; cudaMalloc is forbidden).
// Addressed ONLY from device code (no cudaGetSymbolAddress -> capture-safe).
// ---------------------------------------------------------------------------
__device__ float g_emb[(size_t)BATCH * EMB_TOK * EMB];   // ~491 MB
__device__ float g_s6 [(size_t)BATCH * 16384 * EMB];     // 64 MB
__device__ float g_s7 [(size_t)BATCH * 32768 * EMB];     // 128 MB
__device__ int   g_scat5[BATCH * MIX5];
__device__ int   g_scat6[BATCH * MIX6];
__device__ int   g_scat7[BATCH * MIX7];

// buffer selector: 0 = g_emb, 1 = g_s6, 2 = g_s7, 3 = external (d_out)
__device__ __forceinline__ float* buf_ptr(int sel, float* ext) {
    switch (sel) {
        case 0:  return g_emb;
        case 1:  return g_s6;
        case 2:  return g_s7;
        default: return ext;
    }
}
// rowmap selector: 0 = identity, 1 = scat5, 2 = scat6, 3 = scat7
__device__ __forceinline__ const int* rmap_ptr(int sel) {
    switch (sel) {
        case 1:  return g_scat5;
        case 2:  return g_scat6;
        case 3:  return g_scat7;
        default: return nullptr;
    }
}

// ---------------------------------------------------------------------------
// 1) Embedding: emb = val_tab[v] + dep_tab[d] + pos0[p0] + pos1[p1] + pos2[p2]
//    tokens < 328 go straight to the output; the rest to g_emb scratch.
// ---------------------------------------------------------------------------
__global__ __launch_bounds__(256) void embed_kernel(
    const int* __restrict__ value, const int* __restrict__ depth,
    const int* __restrict__ position,
    const float* __restrict__ val_tab, const float* __restrict__ dep_tab,
    const float* __restrict__ pos_tab,
    float* __restrict__ out)
{
    int s = blockIdx.x;
    int b = blockIdx.y;
    int e = threadIdx.x;
    size_t tok = (size_t)b * S_TOT + s;
    int v  = __ldg(&value[tok]);
    int dp = __ldg(&depth[tok]);
    int p0 = __ldg(&position[tok * 3 + 0]);
    int p1 = __ldg(&position[tok * 3 + 1]);
    int p2 = __ldg(&position[tok * 3 + 2]);

    float r = __ldg(&val_tab[v * EMB + e])
            + __ldg(&dep_tab[dp * EMB + e])
            + __ldg(&pos_tab[(size_t)p0 * EMB + e])
            + __ldg(&pos_tab[((size_t)257 + p1) * EMB + e])
            + __ldg(&pos_tab[((size_t)514 + p2) * EMB + e]);

    if (s < OFF3)
        out[((size_t)b * OUT_TOK + s) * EMB + e] = r;
    else
        g_emb[((size_t)b * EMB_TOK + (s - OFF3)) * EMB + e] = r;
}

// ---------------------------------------------------------------------------
// 2) Ballot-scan: positions of value==2 within a segment -> scatter list
// ---------------------------------------------------------------------------
__global__ __launch_bounds__(1024) void scan_mixed(
    const int* __restrict__ value, int segOff, int segLen,
    int rmapSel, int cap)
{
    int b = blockIdx.x;
    const int* v = value + (size_t)b * S_TOT + segOff;
    int* sc = const_cast<int*>(rmap_ptr(rmapSel)) + b * cap;

    __shared__ int warpTot[32];
    __shared__ int blockBase;
    if (threadIdx.x == 0) blockBase = 0;
    __syncthreads();

    int nWarp = blockDim.x >> 5;
    int lane = threadIdx.x & 31, w = threadIdx.x >> 5;

    for (int start = 0; start < segLen; start += blockDim.x) {
        int i = start + threadIdx.x;
        int m = (i < segLen && v[i] == 2) ? 1 : 0;
        unsigned bal = __ballot_sync(0xffffffffu, m);
        if (lane == 0) warpTot[w] = __popc(bal);
        __syncthreads();
        int woff = 0;
        for (int j = 0; j < w; j++) woff += warpTot[j];
        if (m) {
            int rank = blockBase + woff + __popc(bal & ((1u << lane) - 1));
            sc[rank] = i;
        }
        __syncthreads();
        if (threadIdx.x == 0) {
            int t = 0;
            for (int j = 0; j < nWarp; j++) t += warpTot[j];
            blockBase += t;
        }
        __syncthreads();
    }
}

// ---------------------------------------------------------------------------
// 3) Row copy (substitution base fill): dst[b][r][:] = src[b][r][:]
//    4 rows per block of 256 threads, float4.
// ---------------------------------------------------------------------------
__global__ __launch_bounds__(256) void copy_rows(
    int dSel, size_t dOff, size_t dStride,
    int sSel, size_t sOff, size_t sStride,
    float* __restrict__ ext)
{
    const float* src = buf_ptr(sSel, ext) + sOff;
    float*       dst = buf_ptr(dSel, ext) + dOff;
    int b = blockIdx.y;
    size_t r = (size_t)blockIdx.x * 4 + (threadIdx.x >> 6);
    int c = (threadIdx.x & 63);
    const float4* s = reinterpret_cast<const float4*>(src + (size_t)b * sStride + r * EMB);
    float4*       d = reinterpret_cast<float4*>      (dst + (size_t)b * dStride + r * EMB);
    d[c] = s[c];
}

// ---------------------------------------------------------------------------
// 4) SGEMM: C[b][row][o] = sum_k A[b][row][k] * W[k][o] + bias[o]
//    A: [M, K] row-major per batch; W: [K, 256]; dest row optionally remapped
//    (scatter into substitution targets). BM=BN=128, BK=16, 8x8 per thread.
// ---------------------------------------------------------------------------
__global__ __launch_bounds__(256) void sgemm_conv(
    int aSel, size_t aOff, size_t aStride, int K,
    const float* __restrict__ W, const float* __restrict__ bias,
    int dSel, size_t dOff, size_t dStride,
    int rmapSel, int rmStride,
    float* __restrict__ ext)
{
    constexpr int BM = 128, BN = 128, BK = 16;
    __shared__ float As[BK][BM + 4];
    __shared__ float Bs[BK][BN];

    const float* A = buf_ptr(aSel, ext) + aOff;
    float*       D = buf_ptr(dSel, ext) + dOff;
    const int* rowmap = rmap_ptr(rmapSel);

    int b = blockIdx.z;
    const float* Ab = A + (size_t)b * aStride;
    int rowBlock = blockIdx.x * BM;
    int colBlock = blockIdx.y * BN;

    int tid = threadIdx.x;
    int tx = tid & 15;        // 0..15 -> 8 output cols each
    int ty = tid >> 4;        // 0..15 -> 8 output rows each

    float acc[8][8];
#pragma unroll
    for (int i = 0; i < 8; i++)
#pragma unroll
        for (int j = 0; j < 8; j++) acc[i][j] = 0.f;

    int aRow = tid >> 2;            // 0..63
    int aCol = (tid & 3) * 4;       // 0,4,8,12
    int bRow = tid >> 5;            // 0..7
    int bCol = (tid & 31) * 4;      // 0..124

    for (int k0 = 0; k0 < K; k0 += BK) {
#pragma unroll
        for (int i = 0; i < 2; i++) {
            int r = aRow + i * 64;
            float4 v = *reinterpret_cast<const float4*>(
                &Ab[(size_t)(rowBlock + r) * K + k0 + aCol]);
            As[aCol + 0][r] = v.x;
            As[aCol + 1][r] = v.y;
            As[aCol + 2][r] = v.z;
            As[aCol + 3][r] = v.w;
        }
#pragma unroll
        for (int i = 0; i < 2; i++) {
            int r = bRow + i * 8;
            *reinterpret_cast<float4*>(&Bs[r][bCol]) =
                *reinterpret_cast<const float4*>(&W[(size_t)(k0 + r) * EMB + colBlock + bCol]);
        }
        __syncthreads();

#pragma unroll
        for (int kk = 0; kk < BK; kk++) {
            float4 a0 = *reinterpret_cast<const float4*>(&As[kk][ty * 8]);
            float4 a1 = *reinterpret_cast<const float4*>(&As[kk][ty * 8 + 4]);
            float4 b0 = *reinterpret_cast<const float4*>(&Bs[kk][tx * 8]);
            float4 b1 = *reinterpret_cast<const float4*>(&Bs[kk][tx * 8 + 4]);
            float av[8] = {a0.x, a0.y, a0.z, a0.w, a1.x, a1.y, a1.z, a1.w};
            float bv[8] = {b0.x, b0.y, b0.z, b0.w, b1.x, b1.y, b1.z, b1.w};
#pragma unroll
            for (int m = 0; m < 8; m++)
#pragma unroll
                for (int n = 0; n < 8; n++)
                    acc[m][n] = fmaf(av[m], bv[n], acc[m][n]);
        }
        __syncthreads();
    }

    // epilogue: bias + (optionally scattered) store
#pragma unroll
    for (int m = 0; m < 8; m++) {
        int gRow = rowBlock + ty * 8 + m;
        int dRow = rowmap ? __ldg(&rowmap[b * rmStride + gRow]) : gRow;
        float* dst = D + (size_t)b * dStride + (size_t)dRow * EMB + colBlock + tx * 8;
        float4 o0, o1;
        o0.x = acc[m][0] + __ldg(&bias[colBlock + tx * 8 + 0]);
        o0.y = acc[m][1] + __ldg(&bias[colBlock + tx * 8 + 1]);
        o0.z = acc[m][2] + __ldg(&bias[colBlock + tx * 8 + 2]);
        o0.w = acc[m][3] + __ldg(&bias[colBlock + tx * 8 + 3]);
        o1.x = acc[m][4] + __ldg(&bias[colBlock + tx * 8 + 4]);
        o1.y = acc[m][5] + __ldg(&bias[colBlock + tx * 8 + 5]);
        o1.z = acc[m][6] + __ldg(&bias[colBlock + tx * 8 + 6]);
        o1.w = acc[m][7] + __ldg(&bias[colBlock + tx * 8 + 7]);
        *reinterpret_cast<float4*>(dst)     = o0;
        *reinterpret_cast<float4*>(dst + 4) = o1;
    }
}

// ---------------------------------------------------------------------------
// Host orchestration — kernel launches ONLY (graph-capture safe).
// ---------------------------------------------------------------------------
extern "C" void kernel_launch(void* const* d_in, const int* in_sizes, int n_in,
                              void* d_out, int out_size)
{
    const int*   value    = (const int*)  d_in[0];
    const int*   depth    = (const int*)  d_in[1];
    const int*   position = (const int*)  d_in[2];
    const float* val_tab  = (const float*)d_in[3];
    const float* dep_tab  = (const float*)d_in[4];
    const float* pos_tab  = (const float*)d_in[5];
    const float* W4  = (const float*)d_in[6];   const float* b4  = (const float*)d_in[7];
    const float* W5  = (const float*)d_in[8];   const float* b5  = (const float*)d_in[9];
    const float* W6  = (const float*)d_in[10];  const float* b6  = (const float*)d_in[11];
    const float* W7a = (const float*)d_in[12];  const float* b7a = (const float*)d_in[13];
    const float* W7b = (const float*)d_in[14];  const float* b7b = (const float*)d_in[15];
    const float* W8a = (const float*)d_in[16];  const float* b8a = (const float*)d_in[17];
    const float* W8b = (const float*)d_in[18];  const float* b8b = (const float*)d_in[19];
    float* out = (float*)d_out;

    const size_t embStride = (size_t)EMB_TOK * EMB;
    const size_t outStride = (size_t)OUT_TOK * EMB;
    const size_t s6Stride  = (size_t)16384 * EMB;
    const size_t s7Stride  = (size_t)32768 * EMB;

    // 1) embeddings (also writes identity segments 1..3 to out)
    {
        dim3 grid(S_TOT, BATCH);
        embed_kernel<<<grid, 256>>>(value, depth, position, val_tab, dep_tab,
                                    pos_tab, out);
    }

    // 2) scatter lists for mixed tokens of segments 5, 6, 7
    scan_mixed<<<BATCH, 1024>>>(value, OFF4, 4096,  1, MIX5);
    scan_mixed<<<BATCH, 1024>>>(value, OFF5, 16384, 2, MIX6);
    scan_mixed<<<BATCH, 1024>>>(value, OFF6, 32768, 3, MIX7);

    // 3) substitution base fills
    {
        dim3 g5(4096 / 4, BATCH), g6(16384 / 4, BATCH), g7(32768 / 4, BATCH);
        // out[O6] = emb5 ; out[O7] = emb5 ; out[O8] = emb6
        copy_rows<<<g5, 256>>>(3, (size_t)O6 * EMB, outStride,
                               0, (size_t)E5_OFF * EMB, embStride, out);
        copy_rows<<<g5, 256>>>(3, (size_t)O7 * EMB, outStride,
                               0, (size_t)E5_OFF * EMB, embStride, out);
        copy_rows<<<g6, 256>>>(3, (size_t)O8 * EMB, outStride,
                               0, (size_t)E6_OFF * EMB, embStride, out);
        // s6 = emb6 ; s7 = emb7
        copy_rows<<<g6, 256>>>(1, 0, s6Stride,
                               0, (size_t)E6_OFF * EMB, embStride, out);
        copy_rows<<<g7, 256>>>(2, 0, s7Stride,
                               0, (size_t)E7_OFF * EMB, embStride, out);
    }

    // 4) conv GEMMs (grid: M/128 x 2 x BATCH)
    auto launch_gemm = [&](int aSel, size_t aOff, size_t aStr, int M, int K,
                           const float* W, const float* bias,
                           int dSel, size_t dOff, size_t dStr,
                           int rmapSel, int rmStr) {
        dim3 grid(M / 128, 2, BATCH);
        sgemm_conv<<<grid, 256>>>(aSel, aOff, aStr, K, W, bias,
                                  dSel, dOff, dStr, rmapSel, rmStr, out);
    };

    // depth 4: conv(k=4) -> out[O4]
    launch_gemm(0, (size_t)E4_OFF * EMB, embStride, 256, 1024, W4, b4,
                3, (size_t)O4 * EMB, outStride, 0, 0);
    // depth 5: conv(k=8) -> out[O5]
    launch_gemm(0, (size_t)E5_OFF * EMB, embStride, 512, 2048, W5, b5,
                3, (size_t)O5 * EMB, outStride, 0, 0);
    // depth 6: conv(emb6) scattered into out[O6] (base = emb5)
    launch_gemm(0, (size_t)E6_OFF * EMB, embStride, 2048, 2048, W6, b6,
                3, (size_t)O6 * EMB, outStride, 1, MIX5);
    // depth 7: conv(emb7) scattered into s6 (base = emb6)
    launch_gemm(0, (size_t)E7_OFF * EMB, embStride, 4096, 2048, W7a, b7a,
                1, 0, s6Stride, 2, MIX6);
    //          conv(s6) scattered into out[O7] (base = emb5)
    launch_gemm(1, 0, s6Stride, 2048, 2048, W7b, b7b,
                3, (size_t)O7 * EMB, outStride, 1, MIX5);
    // depth 8: conv(emb8) scattered into s7 (base = emb7)
    launch_gemm(0, (size_t)E8_OFF * EMB, embStride, 8192, 2048, W8a, b8a,
                2, 0, s7Stride, 3, MIX7);
    //          conv(s7) scattered into out[O8] (base = emb6)
    launch_gemm(2, 0, s7Stride, 4096, 2048, W8b, b8b,
                3, (size_t)O8 * EMB, outStride, 2, MIX6);

    (void)in_sizes; (void)n_in; (void)out_size;
}

// round 5
// speedup vs baseline: 2.3407x; 2.3407x over previous
#include <cuda_runtime.h>
#include <cuda_bf16.h>
#include <cstdint>
#include <cstddef>

// ---------------------------------------------------------------------------
// Problem constants (fixed shapes)
// ---------------------------------------------------------------------------
#define BATCH   4
#define EMB     256
#define S_TOT   120136
#define OUT_TOK 25672

// token offsets of depth segments 1..8: OFF = {0,8,72,328,1352,5448,21832,54600,120136}
#define OFF3    328
#define OFF4    1352
#define OFF5    5448
#define OFF6    21832
#define OFF7    54600

#define EMB_TOK (S_TOT - OFF3)   // 119808 tokens in scratch

// per-segment token offsets inside g_emb
#define E4_OFF  0
#define E5_OFF  (OFF4 - OFF3)    // 1024
#define E6_OFF  (OFF5 - OFF3)    // 5120
#define E7_OFF  (OFF6 - OFF3)    // 21504
#define E8_OFF  (OFF7 - OFF3)    // 54272

// output region offsets (tokens)
#define O4 328
#define O5 584
#define O6 1096
#define O7 5192
#define O8 9288

#define MIX5 2048
#define MIX6 4096
#define MIX7 8192

// ---------------------------------------------------------------------------
// Static device scratch (no allocations allowed)
// ---------------------------------------------------------------------------
__device__ float g_emb[(size_t)BATCH * EMB_TOK * EMB];   // ~491 MB
__device__ float g_s6 [(size_t)BATCH * 16384 * EMB];     // 64 MB
__device__ float g_s7 [(size_t)BATCH * 32768 * EMB];     // 128 MB
__device__ int   g_scat5[BATCH * MIX5];
__device__ int   g_scat6[BATCH * MIX6];
__device__ int   g_scat7[BATCH * MIX7];

__device__ __forceinline__ float* buf_ptr(int sel, float* ext) {
    switch (sel) {
        case 0:  return g_emb;
        case 1:  return g_s6;
        case 2:  return g_s7;
        default: return ext;
    }
}
__device__ __forceinline__ const int* rmap_ptr(int sel) {
    switch (sel) {
        case 1:  return g_scat5;
        case 2:  return g_scat6;
        case 3:  return g_scat7;
        default: return nullptr;
    }
}

__device__ __forceinline__ float f2tf32(float x) {
    uint32_t u;
    asm("cvt.rna.tf32.f32 %0, %1;" : "=r"(u) : "f"(x));
    return __uint_as_float(u);
}

// ---------------------------------------------------------------------------
// 1) Embedding + fused substitution-base fills.
//    depth<=3 -> out directly; depth5 row also fills out[O6], out[O7];
//    depth6 row also fills out[O8] and s6; depth7 row also fills s7.
// ---------------------------------------------------------------------------
__global__ __launch_bounds__(256) void embed_kernel(
    const int* __restrict__ value, const int* __restrict__ depth,
    const int* __restrict__ position,
    const float* __restrict__ val_tab, const float* __restrict__ dep_tab,
    const float* __restrict__ pos_tab,
    float* __restrict__ out)
{
    int s = blockIdx.x;
    int b = blockIdx.y;
    int e = threadIdx.x;
    size_t tok = (size_t)b * S_TOT + s;
    int v  = __ldg(&value[tok]);
    int dp = __ldg(&depth[tok]);
    int p0 = __ldg(&position[tok * 3 + 0]);
    int p1 = __ldg(&position[tok * 3 + 1]);
    int p2 = __ldg(&position[tok * 3 + 2]);

    float r = __ldg(&val_tab[v * EMB + e])
            + __ldg(&dep_tab[dp * EMB + e])
            + __ldg(&pos_tab[(size_t)p0 * EMB + e])
            + __ldg(&pos_tab[((size_t)257 + p1) * EMB + e])
            + __ldg(&pos_tab[((size_t)514 + p2) * EMB + e]);

    float* ob = out + (size_t)b * OUT_TOK * EMB;

    if (s < OFF3) {
        ob[(size_t)s * EMB + e] = r;
        return;
    }
    g_emb[((size_t)b * EMB_TOK + (s - OFF3)) * EMB + e] = r;

    if (s >= OFF4 && s < OFF5) {                  // depth 5 -> out[O6], out[O7]
        int i = s - OFF4;
        ob[(size_t)(O6 + i) * EMB + e] = r;
        ob[(size_t)(O7 + i) * EMB + e] = r;
    } else if (s >= OFF5 && s < OFF6) {           // depth 6 -> out[O8], s6
        int i = s - OFF5;
        ob[(size_t)(O8 + i) * EMB + e] = r;
        g_s6[((size_t)b * 16384 + i) * EMB + e] = r;
    } else if (s >= OFF6 && s < OFF7) {           // depth 7 -> s7
        int i = s - OFF6;
        g_s7[((size_t)b * 32768 + i) * EMB + e] = r;
    }
}

// ---------------------------------------------------------------------------
// 2) Mixed-token scan: grid (BATCH, 3). Two passes per warp chunk, 1 sync.
// ---------------------------------------------------------------------------
__global__ __launch_bounds__(1024) void scan_mixed_all(const int* __restrict__ value)
{
    int b = blockIdx.x;
    int seg = blockIdx.y;                 // 0->d5, 1->d6, 2->d7
    int segOff = (seg == 0) ? OFF4 : (seg == 1) ? OFF5 : OFF6;
    int segLen = (seg == 0) ? 4096 : (seg == 1) ? 16384 : 32768;
    int cap    = (seg == 0) ? MIX5 : (seg == 1) ? MIX6 : MIX7;
    int* sc = ((seg == 0) ? g_scat5 : (seg == 1) ? g_scat6 : g_scat7) + b * cap;

    const int* v = value + (size_t)b * S_TOT + segOff;
    int w = threadIdx.x >> 5, lane = threadIdx.x & 31;
    int chunk = segLen >> 5;              // 32 warps
    const int* vc = v + w * chunk;

    // pass 1: per-warp count
    int cnt = 0;
    for (int i = lane; i < chunk; i += 32) cnt += (vc[i] == 2);
#pragma unroll
    for (int o = 16; o > 0; o >>= 1) cnt += __shfl_down_sync(0xffffffffu, cnt, o);
    __shared__ int wc[32];
    if (lane == 0) wc[w] = cnt;
    __syncthreads();

    int base = 0;
    for (int j = 0; j < w; j++) base += wc[j];

    // pass 2: emit indices
    for (int i0 = 0; i0 < chunk; i0 += 32) {
        int i = i0 + lane;
        int m = (vc[i] == 2);
        unsigned bal = __ballot_sync(0xffffffffu, m);
        if (m) sc[base + __popc(bal & ((1u << lane) - 1))] = w * chunk + i;
        base += __popc(bal);
    }
}

// ---------------------------------------------------------------------------
// 3) tf32 tensor-core GEMM: C[b][row][n] = sum_k A[b][row][k]*W[k][n] + bias[n]
//    BM=128, BN=128, BK=16. 8 warps (4x2), warp tile 32x64, mma m16n8k8.
//    Double-buffered smem, register prefetch, tf32 conversion at staging.
//    Epilogue: bias + optional row scatter.
// ---------------------------------------------------------------------------
__global__ __launch_bounds__(256, 2) void mma_conv(
    int aSel, size_t aOff, size_t aStride, int K,
    const float* __restrict__ W, const float* __restrict__ bias,
    int dSel, size_t dOff, size_t dStride,
    int rmapSel, int rmStride,
    float* __restrict__ ext)
{
    constexpr int BM = 128, BN = 128, BK = 16;
    __shared__ float As[2][BM][BK + 4];    // stride 20 -> conflict-free frags
    __shared__ float Bs[2][BK][BN + 8];    // stride 136 -> conflict-free frags

    const float* A = buf_ptr(aSel, ext) + aOff;
    float*       D = buf_ptr(dSel, ext) + dOff;
    const int* rowmap = rmap_ptr(rmapSel);

    int b = blockIdx.z;
    const float* Ab = A + (size_t)b * aStride;
    int rowBlock = blockIdx.x * BM;
    int colBlock = blockIdx.y * BN;

    int tid  = threadIdx.x;
    int lane = tid & 31;
    int wid  = tid >> 5;
    int wm   = wid & 3;          // 4 warps along M (32 rows each)
    int wn   = wid >> 2;         // 2 warps along N (64 cols each)

    // staging coords
    int arow = tid >> 2;             // 0..63 (and +64)
    int acol = (tid & 3) * 4;        // 0,4,8,12
    int brow = tid >> 5;             // 0..7 (and +8)
    int bcol = (tid & 31) * 4;       // 0..124

    float acc[2][8][4];
#pragma unroll
    for (int mt = 0; mt < 2; mt++)
#pragma unroll
        for (int nt = 0; nt < 8; nt++)
#pragma unroll
            for (int q = 0; q < 4; q++) acc[mt][nt][q] = 0.f;

    float4 pa0, pa1, pb0, pb1;
    auto ldg_stage = [&](int k0) {
        pa0 = *reinterpret_cast<const float4*>(&Ab[(size_t)(rowBlock + arow) * K + k0 + acol]);
        pa1 = *reinterpret_cast<const float4*>(&Ab[(size_t)(rowBlock + arow + 64) * K + k0 + acol]);
        pb0 = *reinterpret_cast<const float4*>(&W[(size_t)(k0 + brow) * EMB + colBlock + bcol]);
        pb1 = *reinterpret_cast<const float4*>(&W[(size_t)(k0 + brow + 8) * EMB + colBlock + bcol]);
    };
    auto sts_stage = [&](int buf) {
        float4 ca0 = make_float4(f2tf32(pa0.x), f2tf32(pa0.y), f2tf32(pa0.z), f2tf32(pa0.w));
        float4 ca1 = make_float4(f2tf32(pa1.x), f2tf32(pa1.y), f2tf32(pa1.z), f2tf32(pa1.w));
        float4 cb0 = make_float4(f2tf32(pb0.x), f2tf32(pb0.y), f2tf32(pb0.z), f2tf32(pb0.w));
        float4 cb1 = make_float4(f2tf32(pb1.x), f2tf32(pb1.y), f2tf32(pb1.z), f2tf32(pb1.w));
        *reinterpret_cast<float4*>(&As[buf][arow][acol])      = ca0;
        *reinterpret_cast<float4*>(&As[buf][arow + 64][acol]) = ca1;
        *reinterpret_cast<float4*>(&Bs[buf][brow][bcol])      = cb0;
        *reinterpret_cast<float4*>(&Bs[buf][brow + 8][bcol])  = cb1;
    };

    int fr = lane >> 2;          // fragment row/col group
    int fc = lane & 3;

    auto compute = [&](int buf) {
#pragma unroll
        for (int kk = 0; kk < BK; kk += 8) {
            uint32_t afr[2][4];
#pragma unroll
            for (int mt = 0; mt < 2; mt++) {
                int m = wm * 32 + mt * 16 + fr;
                afr[mt][0] = __float_as_uint(As[buf][m][kk + fc]);
                afr[mt][1] = __float_as_uint(As[buf][m + 8][kk + fc]);
                afr[mt][2] = __float_as_uint(As[buf][m][kk + fc + 4]);
                afr[mt][3] = __float_as_uint(As[buf][m + 8][kk + fc + 4]);
            }
            uint32_t bfr[8][2];
#pragma unroll
            for (int nt = 0; nt < 8; nt++) {
                int n = wn * 64 + nt * 8 + fr;
                bfr[nt][0] = __float_as_uint(Bs[buf][kk + fc][n]);
                bfr[nt][1] = __float_as_uint(Bs[buf][kk + fc + 4][n]);
            }
#pragma unroll
            for (int mt = 0; mt < 2; mt++)
#pragma unroll
                for (int nt = 0; nt < 8; nt++) {
                    float* d = acc[mt][nt];
                    asm volatile(
                        "mma.sync.aligned.m16n8k8.row.col.f32.tf32.tf32.f32 "
                        "{%0,%1,%2,%3}, {%4,%5,%6,%7}, {%8,%9}, {%0,%1,%2,%3};\n"
                        : "+f"(d[0]), "+f"(d[1]), "+f"(d[2]), "+f"(d[3])
                        : "r"(afr[mt][0]), "r"(afr[mt][1]), "r"(afr[mt][2]), "r"(afr[mt][3]),
                          "r"(bfr[nt][0]), "r"(bfr[nt][1]));
                }
        }
    };

    // pipeline
    ldg_stage(0);
    sts_stage(0);
    __syncthreads();
    int cur = 0;
    for (int k0 = BK; k0 < K; k0 += BK) {
        ldg_stage(k0);
        compute(cur);
        sts_stage(cur ^ 1);
        __syncthreads();
        cur ^= 1;
    }
    compute(cur);

    // epilogue: bias + (optionally scattered) float2 stores
    int c2 = fc * 2;
#pragma unroll
    for (int mt = 0; mt < 2; mt++) {
        int row0 = rowBlock + wm * 32 + mt * 16 + fr;
        int row1 = row0 + 8;
        int dRow0 = rowmap ? __ldg(&rowmap[b * rmStride + row0]) : row0;
        int dRow1 = rowmap ? __ldg(&rowmap[b * rmStride + row1]) : row1;
        float* base0 = D + (size_t)b * dStride + (size_t)dRow0 * EMB;
        float* base1 = D + (size_t)b * dStride + (size_t)dRow1 * EMB;
#pragma unroll
        for (int nt = 0; nt < 8; nt++) {
            int col = colBlock + wn * 64 + nt * 8 + c2;
            float bx = __ldg(&bias[col]);
            float by = __ldg(&bias[col + 1]);
            float2 v0 = make_float2(acc[mt][nt][0] + bx, acc[mt][nt][1] + by);
            float2 v1 = make_float2(acc[mt][nt][2] + bx, acc[mt][nt][3] + by);
            *reinterpret_cast<float2*>(base0 + col) = v0;
            *reinterpret_cast<float2*>(base1 + col) = v1;
        }
    }
}

// ---------------------------------------------------------------------------
// Host orchestration — kernel launches ONLY (graph-capture safe).
// ---------------------------------------------------------------------------
extern "C" void kernel_launch(void* const* d_in, const int* in_sizes, int n_in,
                              void* d_out, int out_size)
{
    const int*   value    = (const int*)  d_in[0];
    const int*   depth    = (const int*)  d_in[1];
    const int*   position = (const int*)  d_in[2];
    const float* val_tab  = (const float*)d_in[3];
    const float* dep_tab  = (const float*)d_in[4];
    const float* pos_tab  = (const float*)d_in[5];
    const float* W4  = (const float*)d_in[6];   const float* b4  = (const float*)d_in[7];
    const float* W5  = (const float*)d_in[8];   const float* b5  = (const float*)d_in[9];
    const float* W6  = (const float*)d_in[10];  const float* b6  = (const float*)d_in[11];
    const float* W7a = (const float*)d_in[12];  const float* b7a = (const float*)d_in[13];
    const float* W7b = (const float*)d_in[14];  const float* b7b = (const float*)d_in[15];
    const float* W8a = (const float*)d_in[16];  const float* b8a = (const float*)d_in[17];
    const float* W8b = (const float*)d_in[18];  const float* b8b = (const float*)d_in[19];
    float* out = (float*)d_out;

    const size_t embStride = (size_t)EMB_TOK * EMB;
    const size_t outStride = (size_t)OUT_TOK * EMB;
    const size_t s6Stride  = (size_t)16384 * EMB;
    const size_t s7Stride  = (size_t)32768 * EMB;

    // 1) embeddings + fused base fills
    {
        dim3 grid(S_TOT, BATCH);
        embed_kernel<<<grid, 256>>>(value, depth, position, val_tab, dep_tab,
                                    pos_tab, out);
    }

    // 2) scatter lists (one launch for all three segments)
    {
        dim3 grid(BATCH, 3);
        scan_mixed_all<<<grid, 1024>>>(value);
    }

    // 3) conv GEMMs
    auto launch_gemm = [&](int aSel, size_t aOff, size_t aStr, int M, int K,
                           const float* W, const float* bias,
                           int dSel, size_t dOff, size_t dStr,
                           int rmapSel, int rmStr) {
        dim3 grid(M / 128, 2, BATCH);
        mma_conv<<<grid, 256>>>(aSel, aOff, aStr, K, W, bias,
                                dSel, dOff, dStr, rmapSel, rmStr, out);
    };

    // depth 4: conv(k=4) -> out[O4]
    launch_gemm(0, (size_t)E4_OFF * EMB, embStride, 256, 1024, W4, b4,
                3, (size_t)O4 * EMB, outStride, 0, 0);
    // depth 5: conv(k=8) -> out[O5]
    launch_gemm(0, (size_t)E5_OFF * EMB, embStride, 512, 2048, W5, b5,
                3, (size_t)O5 * EMB, outStride, 0, 0);
    // depth 6: conv(emb6) scattered into out[O6] (base = emb5)
    launch_gemm(0, (size_t)E6_OFF * EMB, embStride, 2048, 2048, W6, b6,
                3, (size_t)O6 * EMB, outStride, 1, MIX5);
    // depth 7: conv(emb7) scattered into s6 (base = emb6)
    launch_gemm(0, (size_t)E7_OFF * EMB, embStride, 4096, 2048, W7a, b7a,
                1, 0, s6Stride, 2, MIX6);
    //          conv(s6) scattered into out[O7] (base = emb5)
    launch_gemm(1, 0, s6Stride, 2048, 2048, W7b, b7b,
                3, (size_t)O7 * EMB, outStride, 1, MIX5);
    // depth 8: conv(emb8) scattered into s7 (base = emb7)
    launch_gemm(0, (size_t)E8_OFF * EMB, embStride, 8192, 2048, W8a, b8a,
                2, 0, s7Stride, 3, MIX7);
    //          conv(s7) scattered into out[O8] (base = emb6)
    launch_gemm(2, 0, s7Stride, 4096, 2048, W8b, b8b,
                3, (size_t)O8 * EMB, outStride, 2, MIX6);

    (void)in_sizes; (void)n_in; (void)out_size;
}

// round 6
// speedup vs baseline: 2.8776x; 1.2294x over previous
#include <cuda_runtime.h>
#include <cuda_bf16.h>
#include <cstdint>
#include <cstddef>

// ---------------------------------------------------------------------------
// Problem constants (fixed shapes)
// ---------------------------------------------------------------------------
#define BATCH   4
#define EMB     256
#define S_TOT   120136
#define OUT_TOK 25672

// OFF = {0,8,72,328,1352,5448,21832,54600,120136}
#define OFF3    328
#define OFF4    1352
#define OFF5    5448
#define OFF6    21832
#define OFF7    54600

#define EMB_TOK (S_TOT - OFF3)   // 119808

#define E4_OFF  0
#define E5_OFF  (OFF4 - OFF3)    // 1024
#define E6_OFF  (OFF5 - OFF3)    // 5120
#define E7_OFF  (OFF6 - OFF3)    // 21504
#define E8_OFF  (OFF7 - OFF3)    // 54272

#define O4 328
#define O5 584
#define O6 1096
#define O7 5192
#define O8 9288

#define MIX5 2048
#define MIX6 4096
#define MIX7 8192

// ---------------------------------------------------------------------------
// Static device scratch
// ---------------------------------------------------------------------------
__device__ float g_emb[(size_t)BATCH * EMB_TOK * EMB];
__device__ float g_s6 [(size_t)BATCH * 16384 * EMB];
__device__ float g_s7 [(size_t)BATCH * 32768 * EMB];
__device__ int   g_scat5[BATCH * MIX5];
__device__ int   g_scat6[BATCH * MIX6];
__device__ int   g_scat7[BATCH * MIX7];

__device__ __forceinline__ float* buf_ptr(int sel, float* ext) {
    switch (sel) {
        case 0:  return g_emb;
        case 1:  return g_s6;
        case 2:  return g_s7;
        default: return ext;
    }
}
__device__ __forceinline__ const int* rmap_ptr(int sel) {
    switch (sel) {
        case 1:  return g_scat5;
        case 2:  return g_scat6;
        case 3:  return g_scat7;
        default: return nullptr;
    }
}

// ---------------------------------------------------------------------------
// 1) Embedding + fused substitution-base fills
// ---------------------------------------------------------------------------
__global__ __launch_bounds__(256) void embed_kernel(
    const int* __restrict__ value, const int* __restrict__ depth,
    const int* __restrict__ position,
    const float* __restrict__ val_tab, const float* __restrict__ dep_tab,
    const float* __restrict__ pos_tab,
    float* __restrict__ out)
{
    int s = blockIdx.x;
    int b = blockIdx.y;
    int e = threadIdx.x;
    size_t tok = (size_t)b * S_TOT + s;
    int v  = __ldg(&value[tok]);
    int dp = __ldg(&depth[tok]);
    int p0 = __ldg(&position[tok * 3 + 0]);
    int p1 = __ldg(&position[tok * 3 + 1]);
    int p2 = __ldg(&position[tok * 3 + 2]);

    float r = __ldg(&val_tab[v * EMB + e])
            + __ldg(&dep_tab[dp * EMB + e])
            + __ldg(&pos_tab[(size_t)p0 * EMB + e])
            + __ldg(&pos_tab[((size_t)257 + p1) * EMB + e])
            + __ldg(&pos_tab[((size_t)514 + p2) * EMB + e]);

    float* ob = out + (size_t)b * OUT_TOK * EMB;

    if (s < OFF3) {
        ob[(size_t)s * EMB + e] = r;
        return;
    }
    g_emb[((size_t)b * EMB_TOK + (s - OFF3)) * EMB + e] = r;

    if (s >= OFF4 && s < OFF5) {                  // d5 -> out[O6], out[O7]
        int i = s - OFF4;
        ob[(size_t)(O6 + i) * EMB + e] = r;
        ob[(size_t)(O7 + i) * EMB + e] = r;
    } else if (s >= OFF5 && s < OFF6) {           // d6 -> out[O8], s6
        int i = s - OFF5;
        ob[(size_t)(O8 + i) * EMB + e] = r;
        g_s6[((size_t)b * 16384 + i) * EMB + e] = r;
    } else if (s >= OFF6 && s < OFF7) {           // d7 -> s7
        int i = s - OFF6;
        g_s7[((size_t)b * 32768 + i) * EMB + e] = r;
    }
}

// ---------------------------------------------------------------------------
// 2) Mixed-token scan (one launch, grid (BATCH,3))
// ---------------------------------------------------------------------------
__global__ __launch_bounds__(1024) void scan_mixed_all(const int* __restrict__ value)
{
    int b = blockIdx.x;
    int seg = blockIdx.y;
    int segOff = (seg == 0) ? OFF4 : (seg == 1) ? OFF5 : OFF6;
    int segLen = (seg == 0) ? 4096 : (seg == 1) ? 16384 : 32768;
    int cap    = (seg == 0) ? MIX5 : (seg == 1) ? MIX6 : MIX7;
    int* sc = ((seg == 0) ? g_scat5 : (seg == 1) ? g_scat6 : g_scat7) + b * cap;

    const int* v = value + (size_t)b * S_TOT + segOff;
    int w = threadIdx.x >> 5, lane = threadIdx.x & 31;
    int chunk = segLen >> 5;
    const int* vc = v + w * chunk;

    int cnt = 0;
    for (int i = lane; i < chunk; i += 32) cnt += (vc[i] == 2);
#pragma unroll
    for (int o = 16; o > 0; o >>= 1) cnt += __shfl_down_sync(0xffffffffu, cnt, o);
    __shared__ int wc[32];
    if (lane == 0) wc[w] = cnt;
    __syncthreads();

    int base = 0;
    for (int j = 0; j < w; j++) base += wc[j];

    for (int i0 = 0; i0 < chunk; i0 += 32) {
        int i = i0 + lane;
        int m = (vc[i] == 2);
        unsigned bal = __ballot_sync(0xffffffffu, m);
        if (m) sc[base + __popc(bal & ((1u << lane) - 1))] = w * chunk + i;
        base += __popc(bal);
    }
}

// ---------------------------------------------------------------------------
// 3) Batched tf32 GEMM, cp.async 4-stage pipeline.
//    All independent convs of one dependency level in ONE launch.
//    C[b][row][n] = sum_k A[b][row][k] * W[k][n] + bias[n], row scatter opt.
// ---------------------------------------------------------------------------
struct SegDesc {
    long long aOff;          // element offset into A base buffer
    long long aStride;       // per-batch elements
    int       aSel;
    int       K;
    int       tileStart;     // first M-tile of this segment
    int       rmapSel;
    int       rmStride;
    int       dSel;
    long long dOff;
    long long dStride;
    const float* W;
    const float* bias;
};
struct SegPack { SegDesc s[5]; int n; };

#define STAGES 4
#define BK     16
#define AS_STRIDE 20     // BK + 4 pad (16B-aligned rows)
#define BS_STRIDE 136    // BN + 8 pad (16B-aligned rows)
#define SMEM_FLOATS (STAGES * 128 * AS_STRIDE + STAGES * BK * BS_STRIDE)

__device__ __forceinline__ void cp_async16(uint32_t dst, const void* src) {
    asm volatile("cp.async.cg.shared.global [%0], [%1], 16;\n" :: "r"(dst), "l"(src));
}

__global__ __launch_bounds__(256, 2) void mma_conv_batched(SegPack pack, float* ext)
{
    extern __shared__ float smem[];
    float* As = smem;                               // [STAGES][128][AS_STRIDE]
    float* Bs = smem + STAGES * 128 * AS_STRIDE;    // [STAGES][BK][BS_STRIDE]

    // segment select (uniform across block)
    int tile = blockIdx.x;
    int si = 0;
#pragma unroll
    for (int i = 1; i < 5; i++)
        if (i < pack.n && tile >= pack.s[i].tileStart) si = i;

    __shared__ SegDesc sg;
    if (threadIdx.x == 0) sg = pack.s[si];
    __syncthreads();

    int b = blockIdx.z;
    const float* Ab = buf_ptr(sg.aSel, ext) + sg.aOff + (size_t)b * sg.aStride;
    const float* Wp = sg.W;
    int K = sg.K;
    int rowBlock = (tile - sg.tileStart) * 128;
    int colBlock = blockIdx.y * 128;

    int tid  = threadIdx.x;
    int lane = tid & 31;
    int wid  = tid >> 5;
    int wm   = wid & 3;
    int wn   = wid >> 2;
    int fr   = lane >> 2;
    int fc   = lane & 3;

    uint32_t asBase = (uint32_t)__cvta_generic_to_shared(As);
    uint32_t bsBase = (uint32_t)__cvta_generic_to_shared(Bs);

    auto load_stage = [&](int st, int kt) {
        int k0 = kt * BK;
#pragma unroll
        for (int i = 0; i < 2; i++) {
            int c = tid + i * 256;            // 512 chunks of 16B for A
            int row = c >> 2, cg = (c & 3) * 4;
            cp_async16(asBase + (((st * 128 + row) * AS_STRIDE + cg) << 2),
                       Ab + (size_t)(rowBlock + row) * K + k0 + cg);
        }
#pragma unroll
        for (int i = 0; i < 2; i++) {
            int c = tid + i * 256;            // 512 chunks of 16B for B
            int row = c >> 5, cg = (c & 31) * 4;
            cp_async16(bsBase + (((st * BK + row) * BS_STRIDE + cg) << 2),
                       Wp + (size_t)(k0 + row) * EMB + colBlock + cg);
        }
    };

    float acc[2][8][4];
#pragma unroll
    for (int mt = 0; mt < 2; mt++)
#pragma unroll
        for (int nt = 0; nt < 8; nt++)
#pragma unroll
            for (int q = 0; q < 4; q++) acc[mt][nt][q] = 0.f;

    auto compute = [&](int st) {
        const float* Ast = As + st * 128 * AS_STRIDE;
        const float* Bst = Bs + st * BK * BS_STRIDE;
#pragma unroll
        for (int kk = 0; kk < BK; kk += 8) {
            uint32_t afr[2][4];
#pragma unroll
            for (int mt = 0; mt < 2; mt++) {
                int m = wm * 32 + mt * 16 + fr;
                afr[mt][0] = __float_as_uint(Ast[m * AS_STRIDE + kk + fc]);
                afr[mt][1] = __float_as_uint(Ast[(m + 8) * AS_STRIDE + kk + fc]);
                afr[mt][2] = __float_as_uint(Ast[m * AS_STRIDE + kk + fc + 4]);
                afr[mt][3] = __float_as_uint(Ast[(m + 8) * AS_STRIDE + kk + fc + 4]);
            }
            uint32_t bfr[8][2];
#pragma unroll
            for (int nt = 0; nt < 8; nt++) {
                int n = wn * 64 + nt * 8 + fr;
                bfr[nt][0] = __float_as_uint(Bst[(kk + fc) * BS_STRIDE + n]);
                bfr[nt][1] = __float_as_uint(Bst[(kk + fc + 4) * BS_STRIDE + n]);
            }
#pragma unroll
            for (int mt = 0; mt < 2; mt++)
#pragma unroll
                for (int nt = 0; nt < 8; nt++) {
                    float* d = acc[mt][nt];
                    asm volatile(
                        "mma.sync.aligned.m16n8k8.row.col.f32.tf32.tf32.f32 "
                        "{%0,%1,%2,%3}, {%4,%5,%6,%7}, {%8,%9}, {%0,%1,%2,%3};\n"
                        : "+f"(d[0]), "+f"(d[1]), "+f"(d[2]), "+f"(d[3])
                        : "r"(afr[mt][0]), "r"(afr[mt][1]), "r"(afr[mt][2]), "r"(afr[mt][3]),
                          "r"(bfr[nt][0]), "r"(bfr[nt][1]));
                }
        }
    };

    int KT = K / BK;

    // prologue: stages 0..2
#pragma unroll
    for (int kt = 0; kt < STAGES - 1; kt++) {
        if (kt < KT) load_stage(kt & (STAGES - 1), kt);
        asm volatile("cp.async.commit_group;\n");
    }

    for (int kt = 0; kt < KT; kt++) {
        asm volatile("cp.async.wait_group %0;\n" :: "n"(STAGES - 2));
        __syncthreads();
        compute(kt & (STAGES - 1));
        int nk = kt + STAGES - 1;
        if (nk < KT) load_stage(nk & (STAGES - 1), nk);
        asm volatile("cp.async.commit_group;\n");
    }

    // epilogue: bias + optional row scatter
    float* D = buf_ptr(sg.dSel, ext) + sg.dOff;
    const int* rowmap = rmap_ptr(sg.rmapSel);
    int c2 = fc * 2;
#pragma unroll
    for (int mt = 0; mt < 2; mt++) {
        int row0 = rowBlock + wm * 32 + mt * 16 + fr;
        int row1 = row0 + 8;
        int dRow0 = rowmap ? __ldg(&rowmap[b * sg.rmStride + row0]) : row0;
        int dRow1 = rowmap ? __ldg(&rowmap[b * sg.rmStride + row1]) : row1;
        float* base0 = D + (size_t)b * sg.dStride + (size_t)dRow0 * EMB;
        float* base1 = D + (size_t)b * sg.dStride + (size_t)dRow1 * EMB;
#pragma unroll
        for (int nt = 0; nt < 8; nt++) {
            int col = colBlock + wn * 64 + nt * 8 + c2;
            float bx = __ldg(&sg.bias[col]);
            float by = __ldg(&sg.bias[col + 1]);
            float2 v0 = make_float2(acc[mt][nt][0] + bx, acc[mt][nt][1] + by);
            float2 v1 = make_float2(acc[mt][nt][2] + bx, acc[mt][nt][3] + by);
            *reinterpret_cast<float2*>(base0 + col) = v0;
            *reinterpret_cast<float2*>(base1 + col) = v1;
        }
    }
}

// ---------------------------------------------------------------------------
// Host orchestration — kernel launches only
// ---------------------------------------------------------------------------
extern "C" void kernel_launch(void* const* d_in, const int* in_sizes, int n_in,
                              void* d_out, int out_size)
{
    const int*   value    = (const int*)  d_in[0];
    const int*   depth    = (const int*)  d_in[1];
    const int*   position = (const int*)  d_in[2];
    const float* val_tab  = (const float*)d_in[3];
    const float* dep_tab  = (const float*)d_in[4];
    const float* pos_tab  = (const float*)d_in[5];
    const float* W4  = (const float*)d_in[6];   const float* b4  = (const float*)d_in[7];
    const float* W5  = (const float*)d_in[8];   const float* b5  = (const float*)d_in[9];
    const float* W6  = (const float*)d_in[10];  const float* b6  = (const float*)d_in[11];
    const float* W7a = (const float*)d_in[12];  const float* b7a = (const float*)d_in[13];
    const float* W7b = (const float*)d_in[14];  const float* b7b = (const float*)d_in[15];
    const float* W8a = (const float*)d_in[16];  const float* b8a = (const float*)d_in[17];
    const float* W8b = (const float*)d_in[18];  const float* b8b = (const float*)d_in[19];
    float* out = (float*)d_out;

    const long long embStride = (long long)EMB_TOK * EMB;
    const long long outStride = (long long)OUT_TOK * EMB;
    const long long s6Stride  = (long long)16384 * EMB;
    const long long s7Stride  = (long long)32768 * EMB;

    static bool attrDone = false;
    if (!attrDone) {
        cudaFuncSetAttribute(mma_conv_batched,
                             cudaFuncAttributeMaxDynamicSharedMemorySize,
                             SMEM_FLOATS * (int)sizeof(float));
        attrDone = true;
    }

    // 1) embeddings + fused base fills
    {
        dim3 grid(S_TOT, BATCH);
        embed_kernel<<<grid, 256>>>(value, depth, position, val_tab, dep_tab,
                                    pos_tab, out);
    }

    // 2) scatter lists
    {
        dim3 grid(BATCH, 3);
        scan_mixed_all<<<grid, 1024>>>(value);
    }

    auto mkseg = [](long long aOff, long long aStr, int aSel, int K, int tileStart,
                    int rmapSel, int rmStr, int dSel, long long dOff, long long dStr,
                    const float* W, const float* bias) {
        SegDesc d;
        d.aOff = aOff; d.aStride = aStr; d.aSel = aSel; d.K = K;
        d.tileStart = tileStart; d.rmapSel = rmapSel; d.rmStride = rmStr;
        d.dSel = dSel; d.dOff = dOff; d.dStride = dStr; d.W = W; d.bias = bias;
        return d;
    };

    // 3) level-1 GEMMs (independent): d4, d5, d6, d7a, d8a — one launch
    {
        SegPack p;
        p.n = 5;
        // tiles: 2, 4, 16, 32, 64 -> starts 0, 2, 6, 22, 54 (total 118)
        p.s[0] = mkseg((long long)E4_OFF * EMB, embStride, 0, 1024, 0,
                       0, 0, 3, (long long)O4 * EMB, outStride, W4, b4);
        p.s[1] = mkseg((long long)E5_OFF * EMB, embStride, 0, 2048, 2,
                       0, 0, 3, (long long)O5 * EMB, outStride, W5, b5);
        p.s[2] = mkseg((long long)E6_OFF * EMB, embStride, 0, 2048, 6,
                       1, MIX5, 3, (long long)O6 * EMB, outStride, W6, b6);
        p.s[3] = mkseg((long long)E7_OFF * EMB, embStride, 0, 2048, 22,
                       2, MIX6, 1, 0, s6Stride, W7a, b7a);
        p.s[4] = mkseg((long long)E8_OFF * EMB, embStride, 0, 2048, 54,
                       3, MIX7, 2, 0, s7Stride, W8a, b8a);
        dim3 grid(118, 2, BATCH);
        mma_conv_batched<<<grid, 256, SMEM_FLOATS * sizeof(float)>>>(p, out);
    }

    // 4) level-2 GEMMs (independent of each other): d7b, d8b — one launch
    {
        SegPack p;
        p.n = 2;
        // tiles: 16, 32 -> starts 0, 16 (total 48)
        p.s[0] = mkseg(0, s6Stride, 1, 2048, 0,
                       1, MIX5, 3, (long long)O7 * EMB, outStride, W7b, b7b);
        p.s[1] = mkseg(0, s7Stride, 2, 2048, 16,
                       2, MIX6, 3, (long long)O8 * EMB, outStride, W8b, b8b);
        p.s[2] = p.s[1]; p.s[3] = p.s[1]; p.s[4] = p.s[1];  // padding (unused)
        dim3 grid(48, 2, BATCH);
        mma_conv_batched<<<grid, 256, SMEM_FLOATS * sizeof(float)>>>(p, out);
    }

    (void)in_sizes; (void)n_in; (void)out_size;
}

// round 9
// speedup vs baseline: 3.3948x; 1.1797x over previous
#include <cuda_runtime.h>
#include <cuda_bf16.h>
#include <cstdint>
#include <cstddef>

// ---------------------------------------------------------------------------
// Problem constants (fixed shapes)
// ---------------------------------------------------------------------------
#define BATCH   4
#define EMB     256
#define S_TOT   120136
#define OUT_TOK 25672

// OFF = {0,8,72,328,1352,5448,21832,54600,120136}
#define OFF3    328
#define OFF4    1352
#define OFF5    5448
#define OFF6    21832
#define OFF7    54600

#define EMB_TOK (S_TOT - OFF3)   // 119808

#define E4_OFF  0
#define E5_OFF  (OFF4 - OFF3)    // 1024
#define E6_OFF  (OFF5 - OFF3)    // 5120
#define E7_OFF  (OFF6 - OFF3)    // 21504
#define E8_OFF  (OFF7 - OFF3)    // 54272

#define O4 328
#define O5 584
#define O6 1096
#define O7 5192
#define O8 9288

#define MIX5 2048
#define MIX6 4096
#define MIX7 8192

// ---------------------------------------------------------------------------
// Static device scratch
// ---------------------------------------------------------------------------
__device__ float g_emb[(size_t)BATCH * EMB_TOK * EMB];
__device__ float g_s6 [(size_t)BATCH * 16384 * EMB];
__device__ float g_s7 [(size_t)BATCH * 32768 * EMB];
__device__ int   g_scat5[BATCH * MIX5];
__device__ int   g_scat6[BATCH * MIX6];
__device__ int   g_scat7[BATCH * MIX7];

__device__ __forceinline__ float* buf_ptr(int sel, float* ext) {
    switch (sel) {
        case 0:  return g_emb;
        case 1:  return g_s6;
        case 2:  return g_s7;
        default: return ext;
    }
}
__device__ __forceinline__ const int* rmap_ptr(int sel) {
    switch (sel) {
        case 1:  return g_scat5;
        case 2:  return g_scat6;
        case 3:  return g_scat7;
        default: return nullptr;
    }
}

__device__ __forceinline__ float4 add4(float4 a, float4 b) {
    return make_float4(a.x + b.x, a.y + b.y, a.z + b.z, a.w + b.w);
}

// ---------------------------------------------------------------------------
// 1) Embedding + fused substitution-base fills. Warp-per-token, float4.
//    Each warp: token s; lane handles float4 indices {lane, lane+32}.
// ---------------------------------------------------------------------------
__global__ __launch_bounds__(256) void embed_kernel(
    const int* __restrict__ value, const int* __restrict__ depth,
    const int* __restrict__ position,
    const float4* __restrict__ val_tab, const float4* __restrict__ dep_tab,
    const float4* __restrict__ pos_tab,
    float* __restrict__ out)
{
    int warp = threadIdx.x >> 5;
    int lane = threadIdx.x & 31;
    int s = blockIdx.x * 8 + warp;
    if (s >= S_TOT) return;
    int b = blockIdx.y;

    size_t tok = (size_t)b * S_TOT + s;
    int v  = __ldg(&value[tok]);
    int dp = __ldg(&depth[tok]);
    int p0 = __ldg(&position[tok * 3 + 0]);
    int p1 = __ldg(&position[tok * 3 + 1]);
    int p2 = __ldg(&position[tok * 3 + 2]);

    const float4* t_v  = val_tab + (size_t)v  * 64;
    const float4* t_d  = dep_tab + (size_t)dp * 64;
    const float4* t_p0 = pos_tab + (size_t)p0 * 64;
    const float4* t_p1 = pos_tab + ((size_t)257 + p1) * 64;
    const float4* t_p2 = pos_tab + ((size_t)514 + p2) * 64;

    float4 r[2];
#pragma unroll
    for (int j = 0; j < 2; j++) {
        int e4 = j * 32 + lane;
        float4 acc = add4(__ldg(&t_v[e4]), __ldg(&t_d[e4]));
        acc = add4(acc, __ldg(&t_p0[e4]));
        acc = add4(acc, __ldg(&t_p1[e4]));
        r[j] = add4(acc, __ldg(&t_p2[e4]));
    }

    float4* ob = reinterpret_cast<float4*>(out) + (size_t)b * OUT_TOK * 64;

    if (s < OFF3) {
#pragma unroll
        for (int j = 0; j < 2; j++) ob[(size_t)s * 64 + j * 32 + lane] = r[j];
        return;
    }

    float4* ge = reinterpret_cast<float4*>(g_emb);
#pragma unroll
    for (int j = 0; j < 2; j++)
        ge[((size_t)b * EMB_TOK + (s - OFF3)) * 64 + j * 32 + lane] = r[j];

    if (s >= OFF4 && s < OFF5) {                  // d5 -> out[O6], out[O7]
        int i = s - OFF4;
#pragma unroll
        for (int j = 0; j < 2; j++) {
            ob[(size_t)(O6 + i) * 64 + j * 32 + lane] = r[j];
            ob[(size_t)(O7 + i) * 64 + j * 32 + lane] = r[j];
        }
    } else if (s >= OFF5 && s < OFF6) {           // d6 -> out[O8], s6
        int i = s - OFF5;
        float4* s6 = reinterpret_cast<float4*>(g_s6);
#pragma unroll
        for (int j = 0; j < 2; j++) {
            ob[(size_t)(O8 + i) * 64 + j * 32 + lane] = r[j];
            s6[((size_t)b * 16384 + i) * 64 + j * 32 + lane] = r[j];
        }
    } else if (s >= OFF6 && s < OFF7) {           // d7 -> s7
        int i = s - OFF6;
        float4* s7 = reinterpret_cast<float4*>(g_s7);
#pragma unroll
        for (int j = 0; j < 2; j++)
            s7[((size_t)b * 32768 + i) * 64 + j * 32 + lane] = r[j];
    }
}

// ---------------------------------------------------------------------------
// 2) Mixed-token scan (one launch, grid (BATCH,3))
// ---------------------------------------------------------------------------
__global__ __launch_bounds__(1024) void scan_mixed_all(const int* __restrict__ value)
{
    int b = blockIdx.x;
    int seg = blockIdx.y;
    int segOff = (seg == 0) ? OFF4 : (seg == 1) ? OFF5 : OFF6;
    int segLen = (seg == 0) ? 4096 : (seg == 1) ? 16384 : 32768;
    int cap    = (seg == 0) ? MIX5 : (seg == 1) ? MIX6 : MIX7;
    int* sc = ((seg == 0) ? g_scat5 : (seg == 1) ? g_scat6 : g_scat7) + b * cap;

    const int* v = value + (size_t)b * S_TOT + segOff;
    int w = threadIdx.x >> 5, lane = threadIdx.x & 31;
    int chunk = segLen >> 5;
    const int* vc = v + w * chunk;

    int cnt = 0;
    for (int i = lane; i < chunk; i += 32) cnt += (vc[i] == 2);
#pragma unroll
    for (int o = 16; o > 0; o >>= 1) cnt += __shfl_down_sync(0xffffffffu, cnt, o);
    __shared__ int wc[32];
    if (lane == 0) wc[w] = cnt;
    __syncthreads();

    int base = 0;
    for (int j = 0; j < w; j++) base += wc[j];

    for (int i0 = 0; i0 < chunk; i0 += 32) {
        int i = i0 + lane;
        int m = (vc[i] == 2);
        unsigned bal = __ballot_sync(0xffffffffu, m);
        if (m) sc[base + __popc(bal & ((1u << lane) - 1))] = w * chunk + i;
        base += __popc(bal);
    }
}

// ---------------------------------------------------------------------------
// 3) Batched tf32 GEMM, cp.async 4-stage, tile 128x256, 512 threads.
// ---------------------------------------------------------------------------
struct SegDesc {
    long long aOff;
    long long aStride;
    int       aSel;
    int       K;
    int       tileStart;
    int       rmapSel;
    int       rmStride;
    int       dSel;
    long long dOff;
    long long dStride;
    const float* W;
    const float* bias;
};
struct SegPack { SegDesc s[5]; int n; };

#define STAGES 4
#define BK     16
#define AS_STRIDE 20     // BK + 4 pad
#define BS_STRIDE 264    // 256 + 8 pad
#define SMEM_FLOATS (STAGES * (128 * AS_STRIDE + BK * BS_STRIDE))

__device__ __forceinline__ void cp_async16(uint32_t dst, const void* src) {
    asm volatile("cp.async.cg.shared.global [%0], [%1], 16;\n" :: "r"(dst), "l"(src));
}

__global__ __launch_bounds__(512, 1) void mma_conv_batched(SegPack pack, float* ext)
{
    extern __shared__ float smem[];
    float* As = smem;                               // [STAGES][128][AS_STRIDE]
    float* Bs = smem + STAGES * 128 * AS_STRIDE;    // [STAGES][BK][BS_STRIDE]

    int tile = blockIdx.x;
    int si = 0;
#pragma unroll
    for (int i = 1; i < 5; i++)
        if (i < pack.n && tile >= pack.s[i].tileStart) si = i;

    __shared__ SegDesc sg;
    if (threadIdx.x == 0) sg = pack.s[si];
    __syncthreads();

    int b = blockIdx.z;
    const float* Ab = buf_ptr(sg.aSel, ext) + sg.aOff + (size_t)b * sg.aStride;
    const float* Wp = sg.W;
    int K = sg.K;
    int rowBlock = (tile - sg.tileStart) * 128;

    int tid  = threadIdx.x;
    int lane = tid & 31;
    int wid  = tid >> 5;        // 0..15
    int wm   = wid & 3;         // 4 warps along M (32 rows)
    int wn   = wid >> 2;        // 4 warps along N (64 cols)
    int fr   = lane >> 2;
    int fc   = lane & 3;

    uint32_t asBase = (uint32_t)__cvta_generic_to_shared(As);
    uint32_t bsBase = (uint32_t)__cvta_generic_to_shared(Bs);

    auto load_stage = [&](int st, int kt) {
        int k0 = kt * BK;
        {   // A: 128 rows x 16 k = 512 float4 chunks, 1 per thread
            int row = tid >> 2, cg = (tid & 3) * 4;
            cp_async16(asBase + (((st * 128 + row) * AS_STRIDE + cg) << 2),
                       Ab + (size_t)(rowBlock + row) * K + k0 + cg);
        }
#pragma unroll
        for (int i = 0; i < 2; i++) {  // B: 16 rows x 256 cols = 1024 chunks
            int c = tid + i * 512;
            int row = c >> 6, cg = (c & 63) * 4;
            cp_async16(bsBase + (((st * BK + row) * BS_STRIDE + cg) << 2),
                       Wp + (size_t)(k0 + row) * EMB + cg);
        }
    };

    float acc[2][8][4];
#pragma unroll
    for (int mt = 0; mt < 2; mt++)
#pragma unroll
        for (int nt = 0; nt < 8; nt++)
#pragma unroll
            for (int q = 0; q < 4; q++) acc[mt][nt][q] = 0.f;

    auto compute = [&](int st) {
        const float* Ast = As + st * 128 * AS_STRIDE;
        const float* Bst = Bs + st * BK * BS_STRIDE;
#pragma unroll
        for (int kk = 0; kk < BK; kk += 8) {
            uint32_t afr[2][4];
#pragma unroll
            for (int mt = 0; mt < 2; mt++) {
                int m = wm * 32 + mt * 16 + fr;
                afr[mt][0] = __float_as_uint(Ast[m * AS_STRIDE + kk + fc]);
                afr[mt][1] = __float_as_uint(Ast[(m + 8) * AS_STRIDE + kk + fc]);
                afr[mt][2] = __float_as_uint(Ast[m * AS_STRIDE + kk + fc + 4]);
                afr[mt][3] = __float_as_uint(Ast[(m + 8) * AS_STRIDE + kk + fc + 4]);
            }
            uint32_t bfr[8][2];
#pragma unroll
            for (int nt = 0; nt < 8; nt++) {
                int n = wn * 64 + nt * 8 + fr;
                bfr[nt][0] = __float_as_uint(Bst[(kk + fc) * BS_STRIDE + n]);
                bfr[nt][1] = __float_as_uint(Bst[(kk + fc + 4) * BS_STRIDE + n]);
            }
#pragma unroll
            for (int mt = 0; mt < 2; mt++)
#pragma unroll
                for (int nt = 0; nt < 8; nt++) {
                    float* d = acc[mt][nt];
                    asm volatile(
                        "mma.sync.aligned.m16n8k8.row.col.f32.tf32.tf32.f32 "
                        "{%0,%1,%2,%3}, {%4,%5,%6,%7}, {%8,%9}, {%0,%1,%2,%3};\n"
                        : "+f"(d[0]), "+f"(d[1]), "+f"(d[2]), "+f"(d[3])
                        : "r"(afr[mt][0]), "r"(afr[mt][1]), "r"(afr[mt][2]), "r"(afr[mt][3]),
                          "r"(bfr[nt][0]), "r"(bfr[nt][1]));
                }
        }
    };

    int KT = K / BK;
#pragma unroll
    for (int kt = 0; kt < STAGES - 1; kt++) {
        if (kt < KT) load_stage(kt & (STAGES - 1), kt);
        asm volatile("cp.async.commit_group;\n");
    }
    for (int kt = 0; kt < KT; kt++) {
        asm volatile("cp.async.wait_group %0;\n" :: "n"(STAGES - 2));
        __syncthreads();
        compute(kt & (STAGES - 1));
        int nk = kt + STAGES - 1;
        if (nk < KT) load_stage(nk & (STAGES - 1), nk);
        asm volatile("cp.async.commit_group;\n");
    }

    // epilogue
    float* D = buf_ptr(sg.dSel, ext) + sg.dOff;
    const int* rowmap = rmap_ptr(sg.rmapSel);
    int c2 = fc * 2;
#pragma unroll
    for (int mt = 0; mt < 2; mt++) {
        int row0 = rowBlock + wm * 32 + mt * 16 + fr;
        int row1 = row0 + 8;
        int dRow0 = rowmap ? __ldg(&rowmap[b * sg.rmStride + row0]) : row0;
        int dRow1 = rowmap ? __ldg(&rowmap[b * sg.rmStride + row1]) : row1;
        float* base0 = D + (size_t)b * sg.dStride + (size_t)dRow0 * EMB;
        float* base1 = D + (size_t)b * sg.dStride + (size_t)dRow1 * EMB;
#pragma unroll
        for (int nt = 0; nt < 8; nt++) {
            int col = wn * 64 + nt * 8 + c2;
            float bx = __ldg(&sg.bias[col]);
            float by = __ldg(&sg.bias[col + 1]);
            float2 v0 = make_float2(acc[mt][nt][0] + bx, acc[mt][nt][1] + by);
            float2 v1 = make_float2(acc[mt][nt][2] + bx, acc[mt][nt][3] + by);
            *reinterpret_cast<float2*>(base0 + col) = v0;
            *reinterpret_cast<float2*>(base1 + col) = v1;
        }
    }
}

// ---------------------------------------------------------------------------
// Host orchestration
// ---------------------------------------------------------------------------
extern "C" void kernel_launch(void* const* d_in, const int* in_sizes, int n_in,
                              void* d_out, int out_size)
{
    const int*   value    = (const int*)  d_in[0];
    const int*   depth    = (const int*)  d_in[1];
    const int*   position = (const int*)  d_in[2];
    const float* val_tab  = (const float*)d_in[3];
    const float* dep_tab  = (const float*)d_in[4];
    const float* pos_tab  = (const float*)d_in[5];
    const float* W4  = (const float*)d_in[6];   const float* b4  = (const float*)d_in[7];
    const float* W5  = (const float*)d_in[8];   const float* b5  = (const float*)d_in[9];
    const float* W6  = (const float*)d_in[10];  const float* b6  = (const float*)d_in[11];
    const float* W7a = (const float*)d_in[12];  const float* b7a = (const float*)d_in[13];
    const float* W7b = (const float*)d_in[14];  const float* b7b = (const float*)d_in[15];
    const float* W8a = (const float*)d_in[16];  const float* b8a = (const float*)d_in[17];
    const float* W8b = (const float*)d_in[18];  const float* b8b = (const float*)d_in[19];
    float* out = (float*)d_out;

    const long long embStride = (long long)EMB_TOK * EMB;
    const long long outStride = (long long)OUT_TOK * EMB;
    const long long s6Stride  = (long long)16384 * EMB;
    const long long s7Stride  = (long long)32768 * EMB;

    static bool attrDone = false;
    if (!attrDone) {
        cudaFuncSetAttribute(mma_conv_batched,
                             cudaFuncAttributeMaxDynamicSharedMemorySize,
                             SMEM_FLOATS * (int)sizeof(float));
        attrDone = true;
    }

    // 1) embeddings + fused base fills (warp-per-token)
    {
        dim3 grid((S_TOT + 7) / 8, BATCH);
        embed_kernel<<<grid, 256>>>(value, depth, position,
                                    (const float4*)val_tab, (const float4*)dep_tab,
                                    (const float4*)pos_tab, out);
    }

    // 2) scatter lists
    {
        dim3 grid(BATCH, 3);
        scan_mixed_all<<<grid, 1024>>>(value);
    }

    auto mkseg = [](long long aOff, long long aStr, int aSel, int K, int tileStart,
                    int rmapSel, int rmStr, int dSel, long long dOff, long long dStr,
                    const float* W, const float* bias) {
        SegDesc d;
        d.aOff = aOff; d.aStride = aStr; d.aSel = aSel; d.K = K;
        d.tileStart = tileStart; d.rmapSel = rmapSel; d.rmStride = rmStr;
        d.dSel = dSel; d.dOff = dOff; d.dStride = dStr; d.W = W; d.bias = bias;
        return d;
    };

    // 3) level-1 GEMMs: d4, d5, d6, d7a, d8a — one launch
    {
        SegPack p;
        p.n = 5;
        // tiles: 2, 4, 16, 32, 64 -> starts 0, 2, 6, 22, 54 (total 118)
        p.s[0] = mkseg((long long)E4_OFF * EMB, embStride, 0, 1024, 0,
                       0, 0, 3, (long long)O4 * EMB, outStride, W4, b4);
        p.s[1] = mkseg((long long)E5_OFF * EMB, embStride, 0, 2048, 2,
                       0, 0, 3, (long long)O5 * EMB, outStride, W5, b5);
        p.s[2] = mkseg((long long)E6_OFF * EMB, embStride, 0, 2048, 6,
                       1, MIX5, 3, (long long)O6 * EMB, outStride, W6, b6);
        p.s[3] = mkseg((long long)E7_OFF * EMB, embStride, 0, 2048, 22,
                       2, MIX6, 1, 0, s6Stride, W7a, b7a);
        p.s[4] = mkseg((long long)E8_OFF * EMB, embStride, 0, 2048, 54,
                       3, MIX7, 2, 0, s7Stride, W8a, b8a);
        dim3 grid(118, 1, BATCH);
        mma_conv_batched<<<grid, 512, SMEM_FLOATS * sizeof(float)>>>(p, out);
    }

    // 4) level-2 GEMMs: d7b, d8b — one launch
    {
        SegPack p;
        p.n = 2;
        p.s[0] = mkseg(0, s6Stride, 1, 2048, 0,
                       1, MIX5, 3, (long long)O7 * EMB, outStride, W7b, b7b);
        p.s[1] = mkseg(0, s7Stride, 2, 2048, 16,
                       2, MIX6, 3, (long long)O8 * EMB, outStride, W8b, b8b);
        p.s[2] = p.s[1]; p.s[3] = p.s[1]; p.s[4] = p.s[1];
        dim3 grid(48, 1, BATCH);
        mma_conv_batched<<<grid, 512, SMEM_FLOATS * sizeof(float)>>>(p, out);
    }

    (void)in_sizes; (void)n_in; (void)out_size;
}

// round 10
// speedup vs baseline: 4.1228x; 1.2144x over previous
#include <cuda_runtime.h>
#include <cuda_bf16.h>
#include <cstdint>
#include <cstddef>

// ---------------------------------------------------------------------------
// Problem constants (fixed shapes)
// ---------------------------------------------------------------------------
#define BATCH   4
#define EMB     256
#define S_TOT   120136
#define OUT_TOK 25672

// OFF = {0,8,72,328,1352,5448,21832,54600,120136}
#define OFF3    328
#define OFF4    1352
#define OFF5    5448
#define OFF6    21832
#define OFF7    54600

#define EMB_TOK (S_TOT - OFF3)   // 119808

#define E4_OFF  0
#define E5_OFF  (OFF4 - OFF3)    // 1024
#define E6_OFF  (OFF5 - OFF3)    // 5120
#define E7_OFF  (OFF6 - OFF3)    // 21504
#define E8_OFF  (OFF7 - OFF3)    // 54272

#define O4 328
#define O5 584
#define O6 1096
#define O7 5192
#define O8 9288

#define MIX5 2048
#define MIX6 4096
#define MIX7 8192

// ---------------------------------------------------------------------------
// Static device scratch
// ---------------------------------------------------------------------------
__device__ float g_emb[(size_t)BATCH * EMB_TOK * EMB];
__device__ float g_s6 [(size_t)BATCH * 16384 * EMB];
__device__ float g_s7 [(size_t)BATCH * 32768 * EMB];
__device__ int   g_scat5[BATCH * MIX5];
__device__ int   g_scat6[BATCH * MIX6];
__device__ int   g_scat7[BATCH * MIX7];

__device__ __forceinline__ float* buf_ptr(int sel, float* ext) {
    switch (sel) {
        case 0:  return g_emb;
        case 1:  return g_s6;
        case 2:  return g_s7;
        default: return ext;
    }
}
__device__ __forceinline__ const int* rmap_ptr(int sel) {
    switch (sel) {
        case 1:  return g_scat5;
        case 2:  return g_scat6;
        case 3:  return g_scat7;
        default: return nullptr;
    }
}

__device__ __forceinline__ float4 add4(float4 a, float4 b) {
    return make_float4(a.x + b.x, a.y + b.y, a.z + b.z, a.w + b.w);
}

// ---------------------------------------------------------------------------
// 1) Embedding + fused substitution-base fills. Warp-per-token, float4.
// ---------------------------------------------------------------------------
__global__ __launch_bounds__(256) void embed_kernel(
    const int* __restrict__ value, const int* __restrict__ depth,
    const int* __restrict__ position,
    const float4* __restrict__ val_tab, const float4* __restrict__ dep_tab,
    const float4* __restrict__ pos_tab,
    float* __restrict__ out)
{
    int warp = threadIdx.x >> 5;
    int lane = threadIdx.x & 31;
    int s = blockIdx.x * 8 + warp;
    if (s >= S_TOT) return;
    int b = blockIdx.y;

    size_t tok = (size_t)b * S_TOT + s;
    int v  = __ldg(&value[tok]);
    int dp = __ldg(&depth[tok]);
    int p0 = __ldg(&position[tok * 3 + 0]);
    int p1 = __ldg(&position[tok * 3 + 1]);
    int p2 = __ldg(&position[tok * 3 + 2]);

    const float4* t_v  = val_tab + (size_t)v  * 64;
    const float4* t_d  = dep_tab + (size_t)dp * 64;
    const float4* t_p0 = pos_tab + (size_t)p0 * 64;
    const float4* t_p1 = pos_tab + ((size_t)257 + p1) * 64;
    const float4* t_p2 = pos_tab + ((size_t)514 + p2) * 64;

    float4 r[2];
#pragma unroll
    for (int j = 0; j < 2; j++) {
        int e4 = j * 32 + lane;
        float4 acc = add4(__ldg(&t_v[e4]), __ldg(&t_d[e4]));
        acc = add4(acc, __ldg(&t_p0[e4]));
        acc = add4(acc, __ldg(&t_p1[e4]));
        r[j] = add4(acc, __ldg(&t_p2[e4]));
    }

    float4* ob = reinterpret_cast<float4*>(out) + (size_t)b * OUT_TOK * 64;

    if (s < OFF3) {
#pragma unroll
        for (int j = 0; j < 2; j++) ob[(size_t)s * 64 + j * 32 + lane] = r[j];
        return;
    }

    float4* ge = reinterpret_cast<float4*>(g_emb);
#pragma unroll
    for (int j = 0; j < 2; j++)
        ge[((size_t)b * EMB_TOK + (s - OFF3)) * 64 + j * 32 + lane] = r[j];

    if (s >= OFF4 && s < OFF5) {                  // d5 -> out[O6], out[O7]
        int i = s - OFF4;
#pragma unroll
        for (int j = 0; j < 2; j++) {
            ob[(size_t)(O6 + i) * 64 + j * 32 + lane] = r[j];
            ob[(size_t)(O7 + i) * 64 + j * 32 + lane] = r[j];
        }
    } else if (s >= OFF5 && s < OFF6) {           // d6 -> out[O8], s6
        int i = s - OFF5;
        float4* s6 = reinterpret_cast<float4*>(g_s6);
#pragma unroll
        for (int j = 0; j < 2; j++) {
            ob[(size_t)(O8 + i) * 64 + j * 32 + lane] = r[j];
            s6[((size_t)b * 16384 + i) * 64 + j * 32 + lane] = r[j];
        }
    } else if (s >= OFF6 && s < OFF7) {           // d7 -> s7
        int i = s - OFF6;
        float4* s7 = reinterpret_cast<float4*>(g_s7);
#pragma unroll
        for (int j = 0; j < 2; j++)
            s7[((size_t)b * 32768 + i) * 64 + j * 32 + lane] = r[j];
    }
}

// ---------------------------------------------------------------------------
// 2) Mixed-token scan (one launch, grid (BATCH,3))
// ---------------------------------------------------------------------------
__global__ __launch_bounds__(1024) void scan_mixed_all(const int* __restrict__ value)
{
    int b = blockIdx.x;
    int seg = blockIdx.y;
    int segOff = (seg == 0) ? OFF4 : (seg == 1) ? OFF5 : OFF6;
    int segLen = (seg == 0) ? 4096 : (seg == 1) ? 16384 : 32768;
    int cap    = (seg == 0) ? MIX5 : (seg == 1) ? MIX6 : MIX7;
    int* sc = ((seg == 0) ? g_scat5 : (seg == 1) ? g_scat6 : g_scat7) + b * cap;

    const int* v = value + (size_t)b * S_TOT + segOff;
    int w = threadIdx.x >> 5, lane = threadIdx.x & 31;
    int chunk = segLen >> 5;
    const int* vc = v + w * chunk;

    int cnt = 0;
    for (int i = lane; i < chunk; i += 32) cnt += (vc[i] == 2);
#pragma unroll
    for (int o = 16; o > 0; o >>= 1) cnt += __shfl_down_sync(0xffffffffu, cnt, o);
    __shared__ int wc[32];
    if (lane == 0) wc[w] = cnt;
    __syncthreads();

    int base = 0;
    for (int j = 0; j < w; j++) base += wc[j];

    for (int i0 = 0; i0 < chunk; i0 += 32) {
        int i = i0 + lane;
        int m = (vc[i] == 2);
        unsigned bal = __ballot_sync(0xffffffffu, m);
        if (m) sc[base + __popc(bal & ((1u << lane) - 1))] = w * chunk + i;
        base += __popc(bal);
    }
}

// ---------------------------------------------------------------------------
// 3) Batched tf32 GEMM. Block 128x128, 4 warps, warp tile 64x64,
//    BK=16, cp.async 4-stage, A-fragments via ldmatrix.x4.
// ---------------------------------------------------------------------------
struct SegDesc {
    long long aOff;
    long long aStride;
    int       aSel;
    int       K;
    int       tileStart;
    int       rmapSel;
    int       rmStride;
    int       dSel;
    long long dOff;
    long long dStride;
    const float* W;
    const float* bias;
};
struct SegPack { SegDesc s[5]; int n; };

#define STAGES 4
#define BK     16
#define AS_STRIDE 20     // 80 B rows: 16B-aligned, conflict-free for ldmatrix
#define BS_STRIDE 136    // 128 + 8 pad
#define SMEM_FLOATS (STAGES * (128 * AS_STRIDE + BK * BS_STRIDE))

__device__ __forceinline__ void cp_async16(uint32_t dst, const void* src) {
    asm volatile("cp.async.cg.shared.global [%0], [%1], 16;\n" :: "r"(dst), "l"(src));
}

__global__ __launch_bounds__(128, 2) void mma_conv_batched(SegPack pack, float* ext)
{
    extern __shared__ float smem[];
    float* As = smem;                               // [STAGES][128][AS_STRIDE]
    float* Bs = smem + STAGES * 128 * AS_STRIDE;    // [STAGES][BK][BS_STRIDE]

    int tile = blockIdx.x;
    int si = 0;
#pragma unroll
    for (int i = 1; i < 5; i++)
        if (i < pack.n && tile >= pack.s[i].tileStart) si = i;

    __shared__ SegDesc sg;
    if (threadIdx.x == 0) sg = pack.s[si];
    __syncthreads();

    int b = blockIdx.z;
    const float* Ab = buf_ptr(sg.aSel, ext) + sg.aOff + (size_t)b * sg.aStride;
    const float* Wp = sg.W;
    int K = sg.K;
    int rowBlock = (tile - sg.tileStart) * 128;
    int colBlock = blockIdx.y * 128;

    int tid  = threadIdx.x;
    int lane = tid & 31;
    int wid  = tid >> 5;        // 0..3
    int wm   = wid & 1;         // 2 warps along M (64 rows each)
    int wn   = wid >> 1;        // 2 warps along N (64 cols each)
    int fr   = lane >> 2;
    int fc   = lane & 3;

    uint32_t asBase = (uint32_t)__cvta_generic_to_shared(As);
    uint32_t bsBase = (uint32_t)__cvta_generic_to_shared(Bs);

    auto load_stage = [&](int st, int kt) {
        int k0 = kt * BK;
#pragma unroll
        for (int i = 0; i < 4; i++) {   // A: 128 rows x 4 float4 = 512 chunks
            int c = tid + i * 128;
            int row = c >> 2, cg = (c & 3) * 4;
            cp_async16(asBase + (((st * 128 + row) * AS_STRIDE + cg) << 2),
                       Ab + (size_t)(rowBlock + row) * K + k0 + cg);
        }
#pragma unroll
        for (int i = 0; i < 4; i++) {   // B: 16 rows x 32 float4 = 512 chunks
            int c = tid + i * 128;
            int row = c >> 5, cg = (c & 31) * 4;
            cp_async16(bsBase + (((st * BK + row) * BS_STRIDE + cg) << 2),
                       Wp + (size_t)(k0 + row) * EMB + colBlock + cg);
        }
    };

    float acc[4][8][4];
#pragma unroll
    for (int mt = 0; mt < 4; mt++)
#pragma unroll
        for (int nt = 0; nt < 8; nt++)
#pragma unroll
            for (int q = 0; q < 4; q++) acc[mt][nt][q] = 0.f;

    // ldmatrix lane addressing: row = m0 + (lane & 15), col = kk + (lane>>4)*4
    int lmRow = lane & 15;
    int lmColSel = (lane >> 4) * 4;

    auto compute = [&](int st) {
        const float* Bst = Bs + st * BK * BS_STRIDE;
        uint32_t aStage = asBase + ((st * 128) * AS_STRIDE << 2);
#pragma unroll
        for (int kk = 0; kk < BK; kk += 8) {
            uint32_t afr[4][4];
#pragma unroll
            for (int mt = 0; mt < 4; mt++) {
                int m = wm * 64 + mt * 16 + lmRow;
                uint32_t addr = aStage + ((m * AS_STRIDE + kk + lmColSel) << 2);
                asm volatile(
                    "ldmatrix.sync.aligned.m8n8.x4.shared.b16 {%0,%1,%2,%3}, [%4];\n"
                    : "=r"(afr[mt][0]), "=r"(afr[mt][1]),
                      "=r"(afr[mt][2]), "=r"(afr[mt][3])
                    : "r"(addr));
            }
            uint32_t bfr[8][2];
#pragma unroll
            for (int nt = 0; nt < 8; nt++) {
                int n = wn * 64 + nt * 8 + fr;
                bfr[nt][0] = __float_as_uint(Bst[(kk + fc) * BS_STRIDE + n]);
                bfr[nt][1] = __float_as_uint(Bst[(kk + fc + 4) * BS_STRIDE + n]);
            }
#pragma unroll
            for (int mt = 0; mt < 4; mt++)
#pragma unroll
                for (int nt = 0; nt < 8; nt++) {
                    float* d = acc[mt][nt];
                    asm volatile(
                        "mma.sync.aligned.m16n8k8.row.col.f32.tf32.tf32.f32 "
                        "{%0,%1,%2,%3}, {%4,%5,%6,%7}, {%8,%9}, {%0,%1,%2,%3};\n"
                        : "+f"(d[0]), "+f"(d[1]), "+f"(d[2]), "+f"(d[3])
                        : "r"(afr[mt][0]), "r"(afr[mt][1]), "r"(afr[mt][2]), "r"(afr[mt][3]),
                          "r"(bfr[nt][0]), "r"(bfr[nt][1]));
                }
        }
    };

    int KT = K / BK;
#pragma unroll
    for (int kt = 0; kt < STAGES - 1; kt++) {
        if (kt < KT) load_stage(kt & (STAGES - 1), kt);
        asm volatile("cp.async.commit_group;\n");
    }
    for (int kt = 0; kt < KT; kt++) {
        asm volatile("cp.async.wait_group %0;\n" :: "n"(STAGES - 2));
        __syncthreads();
        compute(kt & (STAGES - 1));
        int nk = kt + STAGES - 1;
        if (nk < KT) load_stage(nk & (STAGES - 1), nk);
        asm volatile("cp.async.commit_group;\n");
    }

    // epilogue: bias + optional row scatter
    float* D = buf_ptr(sg.dSel, ext) + sg.dOff;
    const int* rowmap = rmap_ptr(sg.rmapSel);
    int c2 = fc * 2;
#pragma unroll
    for (int mt = 0; mt < 4; mt++) {
        int row0 = rowBlock + wm * 64 + mt * 16 + fr;
        int row1 = row0 + 8;
        int dRow0 = rowmap ? __ldg(&rowmap[b * sg.rmStride + row0]) : row0;
        int dRow1 = rowmap ? __ldg(&rowmap[b * sg.rmStride + row1]) : row1;
        float* base0 = D + (size_t)b * sg.dStride + (size_t)dRow0 * EMB;
        float* base1 = D + (size_t)b * sg.dStride + (size_t)dRow1 * EMB;
#pragma unroll
        for (int nt = 0; nt < 8; nt++) {
            int col = colBlock + wn * 64 + nt * 8 + c2;
            float bx = __ldg(&sg.bias[col]);
            float by = __ldg(&sg.bias[col + 1]);
            float2 v0 = make_float2(acc[mt][nt][0] + bx, acc[mt][nt][1] + by);
            float2 v1 = make_float2(acc[mt][nt][2] + bx, acc[mt][nt][3] + by);
            *reinterpret_cast<float2*>(base0 + col) = v0;
            *reinterpret_cast<float2*>(base1 + col) = v1;
        }
    }
}

// ---------------------------------------------------------------------------
// Host orchestration
// ---------------------------------------------------------------------------
extern "C" void kernel_launch(void* const* d_in, const int* in_sizes, int n_in,
                              void* d_out, int out_size)
{
    const int*   value    = (const int*)  d_in[0];
    const int*   depth    = (const int*)  d_in[1];
    const int*   position = (const int*)  d_in[2];
    const float* val_tab  = (const float*)d_in[3];
    const float* dep_tab  = (const float*)d_in[4];
    const float* pos_tab  = (const float*)d_in[5];
    const float* W4  = (const float*)d_in[6];   const float* b4  = (const float*)d_in[7];
    const float* W5  = (const float*)d_in[8];   const float* b5  = (const float*)d_in[9];
    const float* W6  = (const float*)d_in[10];  const float* b6  = (const float*)d_in[11];
    const float* W7a = (const float*)d_in[12];  const float* b7a = (const float*)d_in[13];
    const float* W7b = (const float*)d_in[14];  const float* b7b = (const float*)d_in[15];
    const float* W8a = (const float*)d_in[16];  const float* b8a = (const float*)d_in[17];
    const float* W8b = (const float*)d_in[18];  const float* b8b = (const float*)d_in[19];
    float* out = (float*)d_out;

    const long long embStride = (long long)EMB_TOK * EMB;
    const long long outStride = (long long)OUT_TOK * EMB;
    const long long s6Stride  = (long long)16384 * EMB;
    const long long s7Stride  = (long long)32768 * EMB;

    static bool attrDone = false;
    if (!attrDone) {
        cudaFuncSetAttribute(mma_conv_batched,
                             cudaFuncAttributeMaxDynamicSharedMemorySize,
                             SMEM_FLOATS * (int)sizeof(float));
        attrDone = true;
    }

    // 1) embeddings + fused base fills
    {
        dim3 grid((S_TOT + 7) / 8, BATCH);
        embed_kernel<<<grid, 256>>>(value, depth, position,
                                    (const float4*)val_tab, (const float4*)dep_tab,
                                    (const float4*)pos_tab, out);
    }

    // 2) scatter lists
    {
        dim3 grid(BATCH, 3);
        scan_mixed_all<<<grid, 1024>>>(value);
    }

    auto mkseg = [](long long aOff, long long aStr, int aSel, int K, int tileStart,
                    int rmapSel, int rmStr, int dSel, long long dOff, long long dStr,
                    const float* W, const float* bias) {
        SegDesc d;
        d.aOff = aOff; d.aStride = aStr; d.aSel = aSel; d.K = K;
        d.tileStart = tileStart; d.rmapSel = rmapSel; d.rmStride = rmStr;
        d.dSel = dSel; d.dOff = dOff; d.dStride = dStr; d.W = W; d.bias = bias;
        return d;
    };

    // 3) level-1 GEMMs: d4, d5, d6, d7a, d8a — one launch
    {
        SegPack p;
        p.n = 5;
        // M-tiles: 2, 4, 16, 32, 64 -> starts 0, 2, 6, 22, 54 (total 118)
        p.s[0] = mkseg((long long)E4_OFF * EMB, embStride, 0, 1024, 0,
                       0, 0, 3, (long long)O4 * EMB, outStride, W4, b4);
        p.s[1] = mkseg((long long)E5_OFF * EMB, embStride, 0, 2048, 2,
                       0, 0, 3, (long long)O5 * EMB, outStride, W5, b5);
        p.s[2] = mkseg((long long)E6_OFF * EMB, embStride, 0, 2048, 6,
                       1, MIX5, 3, (long long)O6 * EMB, outStride, W6, b6);
        p.s[3] = mkseg((long long)E7_OFF * EMB, embStride, 0, 2048, 22,
                       2, MIX6, 1, 0, s6Stride, W7a, b7a);
        p.s[4] = mkseg((long long)E8_OFF * EMB, embStride, 0, 2048, 54,
                       3, MIX7, 2, 0, s7Stride, W8a, b8a);
        dim3 grid(118, 2, BATCH);
        mma_conv_batched<<<grid, 128, SMEM_FLOATS * sizeof(float)>>>(p, out);
    }

    // 4) level-2 GEMMs: d7b, d8b — one launch
    {
        SegPack p;
        p.n = 2;
        p.s[0] = mkseg(0, s6Stride, 1, 2048, 0,
                       1, MIX5, 3, (long long)O7 * EMB, outStride, W7b, b7b);
        p.s[1] = mkseg(0, s7Stride, 2, 2048, 16,
                       2, MIX6, 3, (long long)O8 * EMB, outStride, W8b, b8b);
        p.s[2] = p.s[1]; p.s[3] = p.s[1]; p.s[4] = p.s[1];
        dim3 grid(48, 2, BATCH);
        mma_conv_batched<<<grid, 128, SMEM_FLOATS * sizeof(float)>>>(p, out);
    }

    (void)in_sizes; (void)n_in; (void)out_size;
}

// round 13
// speedup vs baseline: 4.4319x; 1.0750x over previous
#include <cuda_runtime.h>
#include <cuda_bf16.h>
#include <cstdint>
#include <cstddef>

// ---------------------------------------------------------------------------
// Problem constants (fixed shapes)
// ---------------------------------------------------------------------------
#define BATCH   4
#define EMB     256
#define S_TOT   120136
#define OUT_TOK 25672

// OFF = {0,8,72,328,1352,5448,21832,54600,120136}
#define OFF3    328
#define OFF4    1352
#define OFF5    5448
#define OFF6    21832
#define OFF7    54600

#define EMB_TOK (S_TOT - OFF3)   // 119808

#define E4_OFF  0
#define E5_OFF  (OFF4 - OFF3)    // 1024
#define E6_OFF  (OFF5 - OFF3)    // 5120
#define E7_OFF  (OFF6 - OFF3)    // 21504
#define E8_OFF  (OFF7 - OFF3)    // 54272

#define O4 328
#define O5 584
#define O6 1096
#define O7 5192
#define O8 9288

#define MIX5 2048
#define MIX6 4096
#define MIX7 8192

// transposed-weight offsets in g_wt (floats): w4 is 1024x256, rest 2048x256
#define WT4  0LL
#define WT5  262144LL
#define WT6  786432LL
#define WT7A 1310720LL
#define WT7B 1835008LL
#define WT8A 2359296LL
#define WT8B 2883584LL
#define WT_TOTAL 3407872LL

// ---------------------------------------------------------------------------
// Static device scratch
// ---------------------------------------------------------------------------
__device__ float g_emb[(size_t)BATCH * EMB_TOK * EMB];
__device__ float g_s6 [(size_t)BATCH * 16384 * EMB];
__device__ float g_s7 [(size_t)BATCH * 32768 * EMB];
__device__ float g_wt [WT_TOTAL];
__device__ int   g_scat5[BATCH * MIX5];
__device__ int   g_scat6[BATCH * MIX6];
__device__ int   g_scat7[BATCH * MIX7];

__device__ __forceinline__ float* buf_ptr(int sel, float* ext) {
    switch (sel) {
        case 0:  return g_emb;
        case 1:  return g_s6;
        case 2:  return g_s7;
        default: return ext;
    }
}
__device__ __forceinline__ const int* rmap_ptr(int sel) {
    switch (sel) {
        case 1:  return g_scat5;
        case 2:  return g_scat6;
        case 3:  return g_scat7;
        default: return nullptr;
    }
}

__device__ __forceinline__ float4 add4(float4 a, float4 b) {
    return make_float4(a.x + b.x, a.y + b.y, a.z + b.z, a.w + b.w);
}

// ---------------------------------------------------------------------------
// 0) Weight transpose: WT[n][k] = W[k][n], per segment. grid (64, 8, 7).
// ---------------------------------------------------------------------------
struct WtPack { const float* W[7]; long long off[7]; int K[7]; };

__global__ __launch_bounds__(256) void transpose_weights(WtPack p)
{
    int seg = blockIdx.z;
    int K = p.K[seg];
    int k0 = blockIdx.x * 32;
    if (k0 >= K) return;
    int n0 = blockIdx.y * 32;
    const float* W = p.W[seg];
    float* WT = g_wt + p.off[seg];

    __shared__ float t[32][33];
    int tx = threadIdx.x & 31;
    int ty = threadIdx.x >> 5;     // 0..7
#pragma unroll
    for (int i = 0; i < 4; i++)
        t[ty + i * 8][tx] = W[(size_t)(k0 + ty + i * 8) * EMB + n0 + tx];
    __syncthreads();
#pragma unroll
    for (int i = 0; i < 4; i++)
        WT[(size_t)(n0 + ty + i * 8) * K + k0 + tx] = t[tx][ty + i * 8];
}

// ---------------------------------------------------------------------------
// 1) Embedding + fused substitution-base fills. Warp-per-token, float4.
// ---------------------------------------------------------------------------
__global__ __launch_bounds__(256) void embed_kernel(
    const int* __restrict__ value, const int* __restrict__ depth,
    const int* __restrict__ position,
    const float4* __restrict__ val_tab, const float4* __restrict__ dep_tab,
    const float4* __restrict__ pos_tab,
    float* __restrict__ out)
{
    int warp = threadIdx.x >> 5;
    int lane = threadIdx.x & 31;
    int s = blockIdx.x * 8 + warp;
    if (s >= S_TOT) return;
    int b = blockIdx.y;

    size_t tok = (size_t)b * S_TOT + s;
    int v  = __ldg(&value[tok]);
    int dp = __ldg(&depth[tok]);
    int p0 = __ldg(&position[tok * 3 + 0]);
    int p1 = __ldg(&position[tok * 3 + 1]);
    int p2 = __ldg(&position[tok * 3 + 2]);

    const float4* t_v  = val_tab + (size_t)v  * 64;
    const float4* t_d  = dep_tab + (size_t)dp * 64;
    const float4* t_p0 = pos_tab + (size_t)p0 * 64;
    const float4* t_p1 = pos_tab + ((size_t)257 + p1) * 64;
    const float4* t_p2 = pos_tab + ((size_t)514 + p2) * 64;

    float4 r[2];
#pragma unroll
    for (int j = 0; j < 2; j++) {
        int e4 = j * 32 + lane;
        float4 acc = add4(__ldg(&t_v[e4]), __ldg(&t_d[e4]));
        acc = add4(acc, __ldg(&t_p0[e4]));
        acc = add4(acc, __ldg(&t_p1[e4]));
        r[j] = add4(acc, __ldg(&t_p2[e4]));
    }

    float4* ob = reinterpret_cast<float4*>(out) + (size_t)b * OUT_TOK * 64;

    if (s < OFF3) {
#pragma unroll
        for (int j = 0; j < 2; j++) ob[(size_t)s * 64 + j * 32 + lane] = r[j];
        return;
    }

    float4* ge = reinterpret_cast<float4*>(g_emb);
#pragma unroll
    for (int j = 0; j < 2; j++)
        ge[((size_t)b * EMB_TOK + (s - OFF3)) * 64 + j * 32 + lane] = r[j];

    if (s >= OFF4 && s < OFF5) {                  // d5 -> out[O6], out[O7]
        int i = s - OFF4;
#pragma unroll
        for (int j = 0; j < 2; j++) {
            ob[(size_t)(O6 + i) * 64 + j * 32 + lane] = r[j];
            ob[(size_t)(O7 + i) * 64 + j * 32 + lane] = r[j];
        }
    } else if (s >= OFF5 && s < OFF6) {           // d6 -> out[O8], s6
        int i = s - OFF5;
        float4* s6 = reinterpret_cast<float4*>(g_s6);
#pragma unroll
        for (int j = 0; j < 2; j++) {
            ob[(size_t)(O8 + i) * 64 + j * 32 + lane] = r[j];
            s6[((size_t)b * 16384 + i) * 64 + j * 32 + lane] = r[j];
        }
    } else if (s >= OFF6 && s < OFF7) {           // d7 -> s7
        int i = s - OFF6;
        float4* s7 = reinterpret_cast<float4*>(g_s7);
#pragma unroll
        for (int j = 0; j < 2; j++)
            s7[((size_t)b * 32768 + i) * 64 + j * 32 + lane] = r[j];
    }
}

// ---------------------------------------------------------------------------
// 2) Mixed-token scan (one launch, grid (BATCH,3))
// ---------------------------------------------------------------------------
__global__ __launch_bounds__(1024) void scan_mixed_all(const int* __restrict__ value)
{
    int b = blockIdx.x;
    int seg = blockIdx.y;
    int segOff = (seg == 0) ? OFF4 : (seg == 1) ? OFF5 : OFF6;
    int segLen = (seg == 0) ? 4096 : (seg == 1) ? 16384 : 32768;
    int cap    = (seg == 0) ? MIX5 : (seg == 1) ? MIX6 : MIX7;
    int* sc = ((seg == 0) ? g_scat5 : (seg == 1) ? g_scat6 : g_scat7) + b * cap;

    const int* v = value + (size_t)b * S_TOT + segOff;
    int w = threadIdx.x >> 5, lane = threadIdx.x & 31;
    int chunk = segLen >> 5;
    const int* vc = v + w * chunk;

    int cnt = 0;
    for (int i = lane; i < chunk; i += 32) cnt += (vc[i] == 2);
#pragma unroll
    for (int o = 16; o > 0; o >>= 1) cnt += __shfl_down_sync(0xffffffffu, cnt, o);
    __shared__ int wc[32];
    if (lane == 0) wc[w] = cnt;
    __syncthreads();

    int base = 0;
    for (int j = 0; j < w; j++) base += wc[j];

    for (int i0 = 0; i0 < chunk; i0 += 32) {
        int i = i0 + lane;
        int m = (vc[i] == 2);
        unsigned bal = __ballot_sync(0xffffffffu, m);
        if (m) sc[base + __popc(bal & ((1u << lane) - 1))] = w * chunk + i;
        base += __popc(bal);
    }
}

// ---------------------------------------------------------------------------
// 3) Batched tf32 GEMM. Block 128x128, 4 warps, warp tile 64x64, BK=16,
//    cp.async 4-stage. BOTH operands via ldmatrix.x4 (B from transposed W).
// ---------------------------------------------------------------------------
struct SegDesc {
    long long aOff;
    long long aStride;
    int       aSel;
    int       K;
    int       tileStart;
    int       rmapSel;
    int       rmStride;
    int       dSel;
    long long dOff;
    long long dStride;
    long long wtOff;          // offset into g_wt (transposed weights [n][k])
    const float* bias;
};
struct SegPack { SegDesc s[5]; int n; };

#define STAGES 4
#define BK     16
#define TS_STRIDE 20     // BK + 4 pad; 80 B rows, 16B-aligned, LDSM-conflict-free
#define TILE_FLOATS (128 * TS_STRIDE)
#define SMEM_FLOATS (STAGES * 2 * TILE_FLOATS)

__device__ __forceinline__ void cp_async16(uint32_t dst, const void* src) {
    asm volatile("cp.async.cg.shared.global [%0], [%1], 16;\n" :: "r"(dst), "l"(src));
}

__global__ __launch_bounds__(128, 2) void mma_conv_batched(SegPack pack, float* ext)
{
    extern __shared__ float smem[];
    float* As = smem;                              // [STAGES][128][TS_STRIDE]
    float* Bs = smem + STAGES * TILE_FLOATS;       // [STAGES][128][TS_STRIDE]

    int tile = blockIdx.x;
    int si = 0;
#pragma unroll
    for (int i = 1; i < 5; i++)
        if (i < pack.n && tile >= pack.s[i].tileStart) si = i;

    __shared__ SegDesc sg;
    if (threadIdx.x == 0) sg = pack.s[si];
    __syncthreads();

    int b = blockIdx.z;
    const float* Ab = buf_ptr(sg.aSel, ext) + sg.aOff + (size_t)b * sg.aStride;
    const float* WT = g_wt + sg.wtOff;
    int K = sg.K;
    int rowBlock = (tile - sg.tileStart) * 128;
    int colBlock = blockIdx.y * 128;

    int tid  = threadIdx.x;
    int lane = tid & 31;
    int wid  = tid >> 5;        // 0..3
    int wm   = wid & 1;         // 2 warps along M (64 rows each)
    int wn   = wid >> 1;        // 2 warps along N (64 cols each)
    int fr   = lane >> 2;
    int fc   = lane & 3;

    uint32_t asBase = (uint32_t)__cvta_generic_to_shared(As);
    uint32_t bsBase = (uint32_t)__cvta_generic_to_shared(Bs);

    auto load_stage = [&](int st, int kt) {
        int k0 = kt * BK;
#pragma unroll
        for (int i = 0; i < 4; i++) {   // A: 128 rows x 4 float4
            int c = tid + i * 128;
            int row = c >> 2, cg = (c & 3) * 4;
            cp_async16(asBase + (((st * 128 + row) * TS_STRIDE + cg) << 2),
                       Ab + (size_t)(rowBlock + row) * K + k0 + cg);
        }
#pragma unroll
        for (int i = 0; i < 4; i++) {   // B (transposed): 128 n-rows x 4 float4
            int c = tid + i * 128;
            int row = c >> 2, cg = (c & 3) * 4;
            cp_async16(bsBase + (((st * 128 + row) * TS_STRIDE + cg) << 2),
                       WT + (size_t)(colBlock + row) * K + k0 + cg);
        }
    };

    float acc[4][8][4];
#pragma unroll
    for (int mt = 0; mt < 4; mt++)
#pragma unroll
        for (int nt = 0; nt < 8; nt++)
#pragma unroll
            for (int q = 0; q < 4; q++) acc[mt][nt][q] = 0.f;

    // A ldmatrix addressing: row = m0 + (lane & 15), col = kk + (lane>>4)*4
    int lmRowA = lane & 15;
    int lmColA = (lane >> 4) * 4;
    // B ldmatrix addressing: row = n0 + (lane>>4)*8 + (lane&7),
    //                        col = kk + ((lane>>3)&1)*4
    int lmRowB = (lane >> 4) * 8 + (lane & 7);
    int lmColB = ((lane >> 3) & 1) * 4;

    auto compute = [&](int st) {
        uint32_t aStage = asBase + ((st * TILE_FLOATS) << 2);
        uint32_t bStage = bsBase + ((st * TILE_FLOATS) << 2);
#pragma unroll
        for (int kk = 0; kk < BK; kk += 8) {
            uint32_t afr[4][4];
#pragma unroll
            for (int mt = 0; mt < 4; mt++) {
                int m = wm * 64 + mt * 16 + lmRowA;
                uint32_t addr = aStage + ((m * TS_STRIDE + kk + lmColA) << 2);
                asm volatile(
                    "ldmatrix.sync.aligned.m8n8.x4.shared.b16 {%0,%1,%2,%3}, [%4];\n"
                    : "=r"(afr[mt][0]), "=r"(afr[mt][1]),
                      "=r"(afr[mt][2]), "=r"(afr[mt][3])
                    : "r"(addr));
            }
            uint32_t bfr[8][2];
#pragma unroll
            for (int j = 0; j < 4; j++) {      // each covers 2 nt (16 n)
                int n = wn * 64 + j * 16 + lmRowB;
                uint32_t addr = bStage + ((n * TS_STRIDE + kk + lmColB) << 2);
                uint32_t r0, r1, r2, r3;
                asm volatile(
                    "ldmatrix.sync.aligned.m8n8.x4.shared.b16 {%0,%1,%2,%3}, [%4];\n"
                    : "=r"(r0), "=r"(r1), "=r"(r2), "=r"(r3)
                    : "r"(addr));
                bfr[j * 2][0] = r0;  bfr[j * 2][1] = r1;
                bfr[j * 2 + 1][0] = r2;  bfr[j * 2 + 1][1] = r3;
            }
#pragma unroll
            for (int mt = 0; mt < 4; mt++)
#pragma unroll
                for (int nt = 0; nt < 8; nt++) {
                    float* d = acc[mt][nt];
                    asm volatile(
                        "mma.sync.aligned.m16n8k8.row.col.f32.tf32.tf32.f32 "
                        "{%0,%1,%2,%3}, {%4,%5,%6,%7}, {%8,%9}, {%0,%1,%2,%3};\n"
                        : "+f"(d[0]), "+f"(d[1]), "+f"(d[2]), "+f"(d[3])
                        : "r"(afr[mt][0]), "r"(afr[mt][1]), "r"(afr[mt][2]), "r"(afr[mt][3]),
                          "r"(bfr[nt][0]), "r"(bfr[nt][1]));
                }
        }
    };

    int KT = K / BK;
#pragma unroll
    for (int kt = 0; kt < STAGES - 1; kt++) {
        if (kt < KT) load_stage(kt & (STAGES - 1), kt);
        asm volatile("cp.async.commit_group;\n");
    }
    for (int kt = 0; kt < KT; kt++) {
        asm volatile("cp.async.wait_group %0;\n" :: "n"(STAGES - 2));
        __syncthreads();
        compute(kt & (STAGES - 1));
        int nk = kt + STAGES - 1;
        if (nk < KT) load_stage(nk & (STAGES - 1), nk);
        asm volatile("cp.async.commit_group;\n");
    }

    // epilogue: bias + optional row scatter
    float* D = buf_ptr(sg.dSel, ext) + sg.dOff;
    const int* rowmap = rmap_ptr(sg.rmapSel);
    int c2 = fc * 2;
#pragma unroll
    for (int mt = 0; mt < 4; mt++) {
        int row0 = rowBlock + wm * 64 + mt * 16 + fr;
        int row1 = row0 + 8;
        int dRow0 = rowmap ? __ldg(&rowmap[b * sg.rmStride + row0]) : row0;
        int dRow1 = rowmap ? __ldg(&rowmap[b * sg.rmStride + row1]) : row1;
        float* base0 = D + (size_t)b * sg.dStride + (size_t)dRow0 * EMB;
        float* base1 = D + (size_t)b * sg.dStride + (size_t)dRow1 * EMB;
#pragma unroll
        for (int nt = 0; nt < 8; nt++) {
            int col = colBlock + wn * 64 + nt * 8 + c2;
            float bx = __ldg(&sg.bias[col]);
            float by = __ldg(&sg.bias[col + 1]);
            float2 v0 = make_float2(acc[mt][nt][0] + bx, acc[mt][nt][1] + by);
            float2 v1 = make_float2(acc[mt][nt][2] + bx, acc[mt][nt][3] + by);
            *reinterpret_cast<float2*>(base0 + col) = v0;
            *reinterpret_cast<float2*>(base1 + col) = v1;
        }
    }
}

// ---------------------------------------------------------------------------
// Host orchestration
// ---------------------------------------------------------------------------
extern "C" void kernel_launch(void* const* d_in, const int* in_sizes, int n_in,
                              void* d_out, int out_size)
{
    const int*   value    = (const int*)  d_in[0];
    const int*   depth    = (const int*)  d_in[1];
    const int*   position = (const int*)  d_in[2];
    const float* val_tab  = (const float*)d_in[3];
    const float* dep_tab  = (const float*)d_in[4];
    const float* pos_tab  = (const float*)d_in[5];
    const float* W4  = (const float*)d_in[6];   const float* b4  = (const float*)d_in[7];
    const float* W5  = (const float*)d_in[8];   const float* b5  = (const float*)d_in[9];
    const float* W6  = (const float*)d_in[10];  const float* b6  = (const float*)d_in[11];
    const float* W7a = (const float*)d_in[12];  const float* b7a = (const float*)d_in[13];
    const float* W7b = (const float*)d_in[14];  const float* b7b = (const float*)d_in[15];
    const float* W8a = (const float*)d_in[16];  const float* b8a = (const float*)d_in[17];
    const float* W8b = (const float*)d_in[18];  const float* b8b = (const float*)d_in[19];
    float* out = (float*)d_out;

    const long long embStride = (long long)EMB_TOK * EMB;
    const long long outStride = (long long)OUT_TOK * EMB;
    const long long s6Stride  = (long long)16384 * EMB;
    const long long s7Stride  = (long long)32768 * EMB;

    static bool attrDone = false;
    if (!attrDone) {
        cudaFuncSetAttribute(mma_conv_batched,
                             cudaFuncAttributeMaxDynamicSharedMemorySize,
                             SMEM_FLOATS * (int)sizeof(float));
        attrDone = true;
    }

    // 0) transpose weights into g_wt
    {
        WtPack wp;
        wp.W[0] = W4;  wp.off[0] = WT4;  wp.K[0] = 1024;
        wp.W[1] = W5;  wp.off[1] = WT5;  wp.K[1] = 2048;
        wp.W[2] = W6;  wp.off[2] = WT6;  wp.K[2] = 2048;
        wp.W[3] = W7a; wp.off[3] = WT7A; wp.K[3] = 2048;
        wp.W[4] = W7b; wp.off[4] = WT7B; wp.K[4] = 2048;
        wp.W[5] = W8a; wp.off[5] = WT8A; wp.K[5] = 2048;
        wp.W[6] = W8b; wp.off[6] = WT8B; wp.K[6] = 2048;
        dim3 grid(64, 8, 7);
        transpose_weights<<<grid, 256>>>(wp);
    }

    // 1) embeddings + fused base fills
    {
        dim3 grid((S_TOT + 7) / 8, BATCH);
        embed_kernel<<<grid, 256>>>(value, depth, position,
                                    (const float4*)val_tab, (const float4*)dep_tab,
                                    (const float4*)pos_tab, out);
    }

    // 2) scatter lists
    {
        dim3 grid(BATCH, 3);
        scan_mixed_all<<<grid, 1024>>>(value);
    }

    auto mkseg = [](long long aOff, long long aStr, int aSel, int K, int tileStart,
                    int rmapSel, int rmStr, int dSel, long long dOff, long long dStr,
                    long long wtOff, const float* bias) {
        SegDesc d;
        d.aOff = aOff; d.aStride = aStr; d.aSel = aSel; d.K = K;
        d.tileStart = tileStart; d.rmapSel = rmapSel; d.rmStride = rmStr;
        d.dSel = dSel; d.dOff = dOff; d.dStride = dStr;
        d.wtOff = wtOff; d.bias = bias;
        return d;
    };

    // 3) level-1 GEMMs: d4, d5, d6, d7a, d8a — one launch
    {
        SegPack p;
        p.n = 5;
        // M-tiles: 2, 4, 16, 32, 64 -> starts 0, 2, 6, 22, 54 (total 118)
        p.s[0] = mkseg((long long)E4_OFF * EMB, embStride, 0, 1024, 0,
                       0, 0, 3, (long long)O4 * EMB, outStride, WT4, b4);
        p.s[1] = mkseg((long long)E5_OFF * EMB, embStride, 0, 2048, 2,
                       0, 0, 3, (long long)O5 * EMB, outStride, WT5, b5);
        p.s[2] = mkseg((long long)E6_OFF * EMB, embStride, 0, 2048, 6,
                       1, MIX5, 3, (long long)O6 * EMB, outStride, WT6, b6);
        p.s[3] = mkseg((long long)E7_OFF * EMB, embStride, 0, 2048, 22,
                       2, MIX6, 1, 0, s6Stride, WT7A, b7a);
        p.s[4] = mkseg((long long)E8_OFF * EMB, embStride, 0, 2048, 54,
                       3, MIX7, 2, 0, s7Stride, WT8A, b8a);
        dim3 grid(118, 2, BATCH);
        mma_conv_batched<<<grid, 128, SMEM_FLOATS * sizeof(float)>>>(p, out);
    }

    // 4) level-2 GEMMs: d7b, d8b — one launch
    {
        SegPack p;
        p.n = 2;
        p.s[0] = mkseg(0, s6Stride, 1, 2048, 0,
                       1, MIX5, 3, (long long)O7 * EMB, outStride, WT7B, b7b);
        p.s[1] = mkseg(0, s7Stride, 2, 2048, 16,
                       2, MIX6, 3, (long long)O8 * EMB, outStride, WT8B, b8b);
        p.s[2] = p.s[1]; p.s[3] = p.s[1]; p.s[4] = p.s[1];
        dim3 grid(48, 2, BATCH);
        mma_conv_batched<<<grid, 128, SMEM_FLOATS * sizeof(float)>>>(p, out);
    }

    (void)in_sizes; (void)n_in; (void)out_size;
}